// round 1
// baseline (speedup 1.0000x reference)
#include <cuda_runtime.h>
#include <math.h>

#define BATCH   8
#define NA      8732
#define NC      21
#define NFG     20
#define TOPK    200
#define PRE     1024
#define CAND    2048
#define GTOP    4096
#define CONF_T  0.5f
#define NMS_T   0.45f

// ---- scratch (static __device__, allocation-free) ----
__device__ float g_boxes[BATCH * NA * 4];            // decoded, clipped xyxy (pixels)
__device__ float g_kscore[BATCH * NFG * TOPK];       // kept scores per (img, class)
__device__ float g_kbox[BATCH * NFG * TOPK * 4];     // kept boxes per (img, class)
__device__ int   g_kcount[BATCH * NFG];              // kept counts

// ============================================================
// Kernel 1: decode + clip. Fully coalesced float4 I/O.
// ============================================================
__global__ void decode_kernel(const float* __restrict__ loc,
                              const float* __restrict__ anch) {
    int idx = blockIdx.x * blockDim.x + threadIdx.x;
    if (idx >= BATCH * NA) return;
    int a = idx % NA;
    float4 l  = reinterpret_cast<const float4*>(loc)[idx];
    float4 an = reinterpret_cast<const float4*>(anch)[a];
    float cx = an.x + l.x * 0.1f * an.z;
    float cy = an.y + l.y * 0.1f * an.w;
    float w  = an.z * expf(l.z * 0.2f);
    float h  = an.w * expf(l.w * 0.2f);
    float x1n = cx - w * 0.5f;
    float y1n = cy - h * 0.5f;
    float x2n = x1n + w;
    float y2n = y1n + h;
    float4 o;
    o.x = fminf(fmaxf(x1n * 300.0f, 0.0f), 299.0f);
    o.y = fminf(fmaxf(y1n * 300.0f, 0.0f), 299.0f);
    o.z = fminf(fmaxf(x2n * 300.0f, 0.0f), 299.0f);
    o.w = fminf(fmaxf(y2n * 300.0f, 0.0f), 299.0f);
    reinterpret_cast<float4*>(g_boxes)[idx] = o;
}

// ============================================================
// Kernel 2: per-(image, class) exact top-1024 selection + greedy NMS.
// One CTA of 1024 threads per (b, class) pair; 160 CTAs.
//
// Selection: scores > 0.5 have float bits in (0x3F000000, ...). Bits are
// monotone in value, so a 256-bin histogram over mantissa bits gives an
// exact bit-threshold with >=1024 elements above it. Compact those
// (~1040 expected) into a 2048 buffer and bitonic-sort packed
// (scorebits<<32 | (65535-anchor)) keys -> exact jax.top_k order
// (desc score, asc index on ties).
//
// NMS: keep[] in shared, one candidate per thread; serial greedy loop
// with uniform early-exit once 200 boxes are kept (exact: the 201st
// kept box of a class can never reach the global top-200).
// ============================================================
__global__ __launch_bounds__(1024) void nms_kernel(const float* __restrict__ cls) {
    const int bc  = blockIdx.x;
    const int b   = bc / NFG;
    const int c20 = bc % NFG;          // foreground class = c20 + 1
    const unsigned tid = threadIdx.x;

    __shared__ int hist[256];
    __shared__ unsigned long long cand[CAND];
    __shared__ float sc[PRE], bx1[PRE], by1[PRE], bx2[PRE], by2[PRE], ar[PRE];
    __shared__ int keep[PRE];
    __shared__ int s_tb, s_cnt;

    if (tid < 256) hist[tid] = 0;
    if (tid == 0)  s_cnt = 0;
    __syncthreads();

    // ---- Phase A: load scores (cached in regs), histogram ----
    float sv[9];
#pragma unroll
    for (int k = 0; k < 9; ++k) {
        int a = (int)tid + k * 1024;
        float s = -1.0f;
        if (a < NA) s = cls[((size_t)(b * NA + a)) * NC + (c20 + 1)];
        sv[k] = s;
        if (s > CONF_T) {
            unsigned bits = __float_as_uint(s);
            unsigned bin  = (bits - 0x3F000000u) >> 15;
            if (bin > 255u) bin = 255u;
            atomicAdd(&hist[bin], 1);
        }
    }
    __syncthreads();

    // ---- Phase B: pick exact bit-threshold bin ----
    if (tid == 0) {
        int total = 0;
        for (int i = 0; i < 256; ++i) total += hist[i];
        int need = total < PRE ? total : PRE;
        int tb = 256, acc = 0;
        if (need > 0) {
            for (int i = 255; i >= 0; --i) {
                acc += hist[i];
                if (acc >= need) { tb = i; break; }
            }
        }
        s_tb = tb;
    }
    __syncthreads();
    const int tb = s_tb;

    // ---- Phase C: compact candidates above threshold bin ----
#pragma unroll
    for (int k = 0; k < 9; ++k) {
        float s = sv[k];
        if (s > CONF_T) {
            unsigned bits = __float_as_uint(s);
            unsigned bin  = (bits - 0x3F000000u) >> 15;
            if (bin > 255u) bin = 255u;
            if ((int)bin >= tb) {
                int p = atomicAdd(&s_cnt, 1);
                if (p < CAND) {
                    int a = (int)tid + k * 1024;
                    cand[p] = ((unsigned long long)bits << 32) |
                              (unsigned)(65535 - a);
                }
            }
        }
    }
    __syncthreads();
    int cnt = s_cnt; if (cnt > CAND) cnt = CAND;
    for (int i = cnt + (int)tid; i < CAND; i += 1024) cand[i] = 0ull;

    // ---- Phase D: bitonic sort ascending (2048 x u64 in shared) ----
    for (unsigned k = 2; k <= CAND; k <<= 1)
        for (unsigned j = k >> 1; j > 0; j >>= 1) {
            __syncthreads();
            for (unsigned i = tid; i < CAND; i += 1024) {
                unsigned l = i ^ j;
                if (l > i) {
                    unsigned long long x = cand[i], y = cand[l];
                    bool up = ((i & k) == 0);
                    if (up ? (x > y) : (x < y)) { cand[i] = y; cand[l] = x; }
                }
            }
        }
    __syncthreads();

    const int count = cnt < PRE ? cnt : PRE;

    // ---- Phase E: fetch candidate boxes (rank r = CAND-1-r in asc order) ----
    float mx1 = 0.f, my1 = 0.f, mx2 = 0.f, my2 = 0.f, mar = 0.f;
    int mkeep = 0;
    if ((int)tid < count) {
        unsigned long long key = cand[CAND - 1 - tid];
        int a = 65535 - (int)(key & 0xFFFFu);
        float4 bb = reinterpret_cast<const float4*>(g_boxes)[b * NA + a];
        mx1 = bb.x; my1 = bb.y; mx2 = bb.z; my2 = bb.w;
        mar = (mx2 - mx1 + 1.0f) * (my2 - my1 + 1.0f);
        sc[tid]  = __uint_as_float((unsigned)(key >> 32));
        bx1[tid] = mx1; by1[tid] = my1; bx2[tid] = mx2; by2[tid] = my2;
        ar[tid]  = mar;
        mkeep = 1;
    }
    keep[tid] = mkeep;
    __syncthreads();

    // ---- Phase F: greedy NMS, early exit at 200 kept ----
    int nkept = 0;   // uniform across threads (driven by shared keep[i])
    for (int i = 0; i < count; ++i) {
        if (!keep[i]) continue;                 // uniform; no writes when skipping
        float ix1 = bx1[i], iy1 = by1[i], ix2 = bx2[i], iy2 = by2[i], ia = ar[i];
        if (tid == 0) {                          // record kept box
            int base = bc * TOPK + nkept;
            g_kscore[base]        = sc[i];
            g_kbox[base * 4 + 0]  = ix1;
            g_kbox[base * 4 + 1]  = iy1;
            g_kbox[base * 4 + 2]  = ix2;
            g_kbox[base * 4 + 3]  = iy2;
        }
        nkept++;
        if (mkeep && (int)tid > i) {             // suppress own candidate
            float xx1 = fmaxf(ix1, mx1), yy1 = fmaxf(iy1, my1);
            float xx2 = fminf(ix2, mx2), yy2 = fminf(iy2, my2);
            float w = fmaxf(xx2 - xx1 + 1.0f, 0.0f);
            float h = fmaxf(yy2 - yy1 + 1.0f, 0.0f);
            float inter = w * h;
            float iou = inter / (ia + mar - inter);
            if (iou > NMS_T) { mkeep = 0; keep[tid] = 0; }
        }
        __syncthreads();
        if (nkept >= TOPK) break;                // uniform register condition
    }
    if (tid == 0) g_kcount[bc] = nkept;
}

// ============================================================
// Kernel 3: per-image global top-200 over 20x200 kept candidates.
// Keys: (scorebits<<32) | (0xFFFFFFFF - (c20*256+slot)) -> descending
// read gives jax flat-index tie-breaking (lower class, earlier kept first).
// Output layout (float32): boxes[8,200,4] | scores[8,200] | labels[8,200].
// ============================================================
__global__ __launch_bounds__(1024) void topk_kernel(float* __restrict__ out) {
    const int b = blockIdx.x;
    const unsigned tid = threadIdx.x;
    __shared__ unsigned long long arr[GTOP];

    for (int idx = (int)tid; idx < GTOP; idx += 1024) {
        unsigned long long key = 0ull;
        if (idx < NFG * TOPK) {
            int c20 = idx / TOPK, slot = idx % TOPK;
            if (slot < g_kcount[b * NFG + c20]) {
                unsigned bits = __float_as_uint(
                    g_kscore[(b * NFG + c20) * TOPK + slot]);
                key = ((unsigned long long)bits << 32) |
                      (0xFFFFFFFFu - (unsigned)(c20 * 256 + slot));
            }
        }
        arr[idx] = key;
    }

    for (unsigned k = 2; k <= GTOP; k <<= 1)
        for (unsigned j = k >> 1; j > 0; j >>= 1) {
            __syncthreads();
            for (unsigned i = tid; i < GTOP; i += 1024) {
                unsigned l = i ^ j;
                if (l > i) {
                    unsigned long long x = arr[i], y = arr[l];
                    bool up = ((i & k) == 0);
                    if (up ? (x > y) : (x < y)) { arr[i] = y; arr[l] = x; }
                }
            }
        }
    __syncthreads();

    if (tid < TOPK) {
        unsigned long long key = arr[GTOP - 1 - tid];
        float b0 = 0.f, b1 = 0.f, b2 = 0.f, b3 = 0.f, sco = 0.f, lab = 0.f;
        if ((key >> 32) != 0ull) {
            unsigned code = 0xFFFFFFFFu - (unsigned)(key & 0xFFFFFFFFu);
            int c20  = (int)(code >> 8);
            int slot = (int)(code & 255u);
            int base = (b * NFG + c20) * TOPK + slot;
            sco = __uint_as_float((unsigned)(key >> 32));
            b0 = g_kbox[base * 4 + 0];
            b1 = g_kbox[base * 4 + 1];
            b2 = g_kbox[base * 4 + 2];
            b3 = g_kbox[base * 4 + 3];
            lab = (float)(c20 + 1);
        }
        int r = (int)tid;
        out[(b * TOPK + r) * 4 + 0] = b0;
        out[(b * TOPK + r) * 4 + 1] = b1;
        out[(b * TOPK + r) * 4 + 2] = b2;
        out[(b * TOPK + r) * 4 + 3] = b3;
        out[BATCH * TOPK * 4 + b * TOPK + r] = sco;
        out[BATCH * TOPK * 5 + b * TOPK + r] = lab;
    }
}

// ============================================================
extern "C" void kernel_launch(void* const* d_in, const int* in_sizes, int n_in,
                              void* d_out, int out_size) {
    const float* cls  = (const float*)d_in[0];  // [8, 8732, 21]
    const float* loc  = (const float*)d_in[1];  // [8, 8732, 4]
    const float* anch = (const float*)d_in[2];  // [8732, 4]
    float* out = (float*)d_out;

    decode_kernel<<<(BATCH * NA + 255) / 256, 256>>>(loc, anch);
    nms_kernel<<<BATCH * NFG, 1024>>>(cls);
    topk_kernel<<<BATCH, 1024>>>(out);
}

// round 2
// speedup vs baseline: 1.2355x; 1.2355x over previous
#include <cuda_runtime.h>
#include <math.h>

#define BATCH   8
#define NA      8732
#define NAP     8736          // padded anchors for transposed layout
#define NC      21
#define NFG     20
#define TOPK    200
#define PRE     1024
#define CAND    2048
#define GCAP    512
#define CONF_T  0.5f
#define NMS_T   0.45f

// ---- scratch (static __device__, allocation-free) ----
__device__ float g_boxes[BATCH * NA * 4];            // decoded, clipped xyxy
__device__ float g_clsT[BATCH * NFG * NAP];          // transposed scores [b][c][a]
__device__ float g_kscore[BATCH * NFG * TOPK];       // kept scores per (img, class)
__device__ float g_kbox[BATCH * NFG * TOPK * 4];     // kept boxes per (img, class)
__device__ int   g_kcount[BATCH * NFG];              // kept counts

#define DEC_BLOCKS ((BATCH * NA + 255) / 256)
#define TR_TILE    128
#define TR_TPB     ((NA + TR_TILE - 1) / TR_TILE)    // 69 tiles per image
#define TR_BLOCKS  (BATCH * TR_TPB)

// ============================================================
// Kernel 1 (fused): decode+clip  AND  transpose cls -> [b][c][a]
// ============================================================
__global__ void prep_kernel(const float* __restrict__ cls,
                            const float* __restrict__ loc,
                            const float* __restrict__ anch) {
    if (blockIdx.x < DEC_BLOCKS) {
        int idx = blockIdx.x * 256 + threadIdx.x;
        if (idx >= BATCH * NA) return;
        int a = idx % NA;
        float4 l  = reinterpret_cast<const float4*>(loc)[idx];
        float4 an = reinterpret_cast<const float4*>(anch)[a];
        float cx = an.x + l.x * 0.1f * an.z;
        float cy = an.y + l.y * 0.1f * an.w;
        float w  = an.z * expf(l.z * 0.2f);
        float h  = an.w * expf(l.w * 0.2f);
        float x1n = cx - w * 0.5f;
        float y1n = cy - h * 0.5f;
        float x2n = x1n + w;
        float y2n = y1n + h;
        float4 o;
        o.x = fminf(fmaxf(x1n * 300.0f, 0.0f), 299.0f);
        o.y = fminf(fmaxf(y1n * 300.0f, 0.0f), 299.0f);
        o.z = fminf(fmaxf(x2n * 300.0f, 0.0f), 299.0f);
        o.w = fminf(fmaxf(y2n * 300.0f, 0.0f), 299.0f);
        reinterpret_cast<float4*>(g_boxes)[idx] = o;
    } else {
        __shared__ float sh[TR_TILE * NC];
        int t = blockIdx.x - DEC_BLOCKS;
        int b = t / TR_TPB, tile = t % TR_TPB;
        int a0 = tile * TR_TILE;
        int n = NA - a0; if (n > TR_TILE) n = TR_TILE;
        const float* src = cls + ((size_t)(b * NA + a0)) * NC;
        for (int i = threadIdx.x; i < n * NC; i += 256) sh[i] = src[i];
        __syncthreads();
        int half = threadIdx.x >> 7;       // 0: classes 0..9, 1: classes 10..19
        int t2 = threadIdx.x & 127;
        if (t2 < n) {
            for (int c = half * 10; c < half * 10 + 10; ++c)
                g_clsT[((size_t)(b * NFG + c)) * NAP + a0 + t2] = sh[t2 * NC + c + 1];
        }
    }
}

// ============================================================
// Kernel 2: per-(image,class) exact top-1024 + chunked greedy NMS.
// 512 threads/CTA, 2 CTAs/SM -> single wave for 160 CTAs.
// ============================================================
__global__ __launch_bounds__(512, 2) void nms_kernel() {
    const int bc  = blockIdx.x;
    const int b   = bc / NFG;
    const int c20 = bc % NFG;
    const int tid = threadIdx.x;

    __shared__ int hist[256];
    __shared__ unsigned long long cand[CAND];
    __shared__ float4 sbox[PRE];
    __shared__ float  sar[PRE], ssc[PRE];
    __shared__ int    salive[PRE];
    __shared__ float4 ck4[32];
    __shared__ float  ckar[32];
    __shared__ int s_tb, s_cnt, s_nck;

    if (tid < 256) hist[tid] = 0;
    if (tid == 0) { s_cnt = 0; s_tb = 256; }
    __syncthreads();

    const float* scol = g_clsT + ((size_t)(b * NFG + c20)) * NAP;

    // ---- A: histogram over float-bit bins (monotone in score) ----
    for (int a = tid; a < NA; a += 512) {
        float s = scol[a];
        if (s > CONF_T) {
            unsigned bin = (__float_as_uint(s) - 0x3F000000u) >> 15;
            if (bin > 255u) bin = 255u;
            atomicAdd(&hist[bin], 1);
        }
    }
    __syncthreads();

    // ---- B: parallel suffix scan; exact bit-threshold bin ----
    for (int off = 1; off < 256; off <<= 1) {
        int v = 0;
        if (tid < 256) v = (tid + off < 256) ? hist[tid + off] : 0;
        __syncthreads();
        if (tid < 256) hist[tid] += v;
        __syncthreads();
    }
    {
        int total = hist[0];
        int need = total < PRE ? total : PRE;
        if (tid < 256 && need > 0) {
            int sfx = hist[tid];
            int nxt = (tid < 255) ? hist[tid + 1] : 0;
            if (sfx >= need && nxt < need) s_tb = tid;
        }
    }
    __syncthreads();
    const int tb = s_tb;

    // ---- C: compact candidates above threshold bin ----
    for (int a = tid; a < NA; a += 512) {
        float s = scol[a];
        if (s > CONF_T) {
            unsigned bits = __float_as_uint(s);
            unsigned bin = (bits - 0x3F000000u) >> 15;
            if (bin > 255u) bin = 255u;
            if ((int)bin >= tb) {
                int p = atomicAdd(&s_cnt, 1);
                if (p < CAND)
                    cand[p] = ((unsigned long long)bits << 32) |
                              (unsigned)(65535 - a);
            }
        }
    }
    __syncthreads();
    int cnt = s_cnt; if (cnt > CAND) cnt = CAND;
    for (int i = cnt + tid; i < CAND; i += 512) cand[i] = 0ull;

    // ---- D: bitonic sort ascending, 2048 x u64, pair-indexed ----
    for (unsigned k = 2; k <= CAND; k <<= 1)
        for (unsigned j = k >> 1; j; j >>= 1) {
            __syncthreads();
            #pragma unroll
            for (int q = 0; q < 2; ++q) {
                unsigned p = (unsigned)tid + (unsigned)q * 512u;
                unsigned i = ((p & ~(j - 1u)) << 1) | (p & (j - 1u));
                unsigned l = i | j;
                unsigned long long x = cand[i], y = cand[l];
                bool up = ((i & k) == 0u);
                if (up ? (x > y) : (x < y)) { cand[i] = y; cand[l] = x; }
            }
        }
    __syncthreads();

    const int count = cnt < PRE ? cnt : PRE;

    // ---- E: fetch candidate boxes, rank r = best-first ----
    const float4* boxes4 = reinterpret_cast<const float4*>(g_boxes);
    float4 obox[2]; float oar[2]; int oalive[2];
    #pragma unroll
    for (int t = 0; t < 2; ++t) {
        int r = 2 * tid + t;
        unsigned long long key = cand[CAND - 1 - r];
        if (key != 0ull) {
            int a = 65535 - (int)(key & 0xFFFFu);
            float4 bb = boxes4[b * NA + a];
            float area = (bb.z - bb.x + 1.0f) * (bb.w - bb.y + 1.0f);
            sbox[r] = bb; sar[r] = area;
            ssc[r] = __uint_as_float((unsigned)(key >> 32));
            salive[r] = 1;
            obox[t] = bb; oar[t] = area; oalive[t] = 1;
        } else {
            float4 z = make_float4(0.f, 0.f, 0.f, 0.f);
            sbox[r] = z; sar[r] = 0.f; ssc[r] = 0.f; salive[r] = 0;
            obox[t] = z; oar[t] = 0.f; oalive[t] = 0;
        }
    }

    // ---- F: chunked greedy NMS (exact), early exit at 200 kept ----
    int nkept = 0;
    const int cchunks = (count + 31) >> 5;
    for (int c = 0; c < cchunks; ++c) {
        __syncthreads();                  // salive / sbox stores visible
        if (tid < 32) {
            int r = (c << 5) + tid;
            int al = salive[r];
            float4 bb = sbox[r];
            float aa = sar[r];
            unsigned keptm = 0u;
            unsigned rem = __ballot_sync(0xFFFFFFFFu, al);
            while (rem) {
                int s = __ffs(rem) - 1;
                rem &= rem - 1u;
                unsigned m = __ballot_sync(0xFFFFFFFFu, al);
                if ((m >> s) & 1u) {      // candidate s survives to its turn
                    keptm |= 1u << s;
                    float ix1 = __shfl_sync(0xFFFFFFFFu, bb.x, s);
                    float iy1 = __shfl_sync(0xFFFFFFFFu, bb.y, s);
                    float ix2 = __shfl_sync(0xFFFFFFFFu, bb.z, s);
                    float iy2 = __shfl_sync(0xFFFFFFFFu, bb.w, s);
                    float ia  = __shfl_sync(0xFFFFFFFFu, aa, s);
                    if (tid > s && al) {
                        float xx1 = fmaxf(ix1, bb.x), yy1 = fmaxf(iy1, bb.y);
                        float xx2 = fminf(ix2, bb.z), yy2 = fminf(iy2, bb.w);
                        float w = fmaxf(xx2 - xx1 + 1.0f, 0.0f);
                        float h = fmaxf(yy2 - yy1 + 1.0f, 0.0f);
                        float inter = w * h;
                        float iou = inter / (ia + aa - inter);
                        if (iou > NMS_T) al = 0;
                    }
                }
            }
            int nck  = __popc(keptm);
            int take = TOPK - nkept; if (take > nck) take = nck;
            int rank = __popc(keptm & ((1u << tid) - 1u));
            if (((keptm >> tid) & 1u) && rank < take) {
                ck4[rank] = bb; ckar[rank] = aa;
                int base = bc * TOPK + nkept + rank;
                g_kscore[base]       = ssc[r];
                g_kbox[base * 4 + 0] = bb.x;
                g_kbox[base * 4 + 1] = bb.y;
                g_kbox[base * 4 + 2] = bb.z;
                g_kbox[base * 4 + 3] = bb.w;
            }
            if (tid == 0) s_nck = take;
        }
        __syncthreads();
        int nck = s_nck;
        nkept += nck;
        if (nkept >= TOPK) break;
        if (nck > 0) {
            int rlim = (c + 1) << 5;
            #pragma unroll
            for (int t = 0; t < 2; ++t) {
                int r = 2 * tid + t;
                if (oalive[t] && r >= rlim) {
                    float4 bb = obox[t]; float aa = oar[t];
                    for (int jj = 0; jj < nck; ++jj) {
                        float4 kb = ck4[jj];
                        float xx1 = fmaxf(kb.x, bb.x), yy1 = fmaxf(kb.y, bb.y);
                        float xx2 = fminf(kb.z, bb.z), yy2 = fminf(kb.w, bb.w);
                        float w = fmaxf(xx2 - xx1 + 1.0f, 0.0f);
                        float h = fmaxf(yy2 - yy1 + 1.0f, 0.0f);
                        float inter = w * h;
                        float iou = inter / (ckar[jj] + aa - inter);
                        if (iou > NMS_T) { oalive[t] = 0; salive[r] = 0; break; }
                    }
                }
            }
        }
    }
    if (tid == 0) g_kcount[bc] = nkept;
}

// ============================================================
// Kernel 3: per-image global top-200 via bit-histogram threshold
// then tiny 512-key bitonic sort. Exact tie-breaking preserved.
// ============================================================
__global__ __launch_bounds__(512) void topk_kernel(float* __restrict__ out) {
    const int b = blockIdx.x;
    const int tid = threadIdx.x;
    __shared__ int hist[256];
    __shared__ unsigned long long buf[GCAP];
    __shared__ int s_cnt, s_tb;
    __shared__ int skc[NFG];

    if (tid < 256) hist[tid] = 0;
    if (tid == 0) { s_cnt = 0; s_tb = 256; }
    if (tid < NFG) skc[tid] = g_kcount[b * NFG + tid];
    __syncthreads();

    for (int idx = tid; idx < NFG * TOPK; idx += 512) {
        int c20 = idx / TOPK, slot = idx % TOPK;
        if (slot < skc[c20]) {
            unsigned bits = __float_as_uint(g_kscore[(b * NFG + c20) * TOPK + slot]);
            unsigned bin = (bits - 0x3F000000u) >> 15;
            if (bin > 255u) bin = 255u;
            atomicAdd(&hist[bin], 1);
        }
    }
    __syncthreads();
    for (int off = 1; off < 256; off <<= 1) {
        int v = 0;
        if (tid < 256) v = (tid + off < 256) ? hist[tid + off] : 0;
        __syncthreads();
        if (tid < 256) hist[tid] += v;
        __syncthreads();
    }
    {
        int total = hist[0];
        int need = total < TOPK ? total : TOPK;
        if (tid < 256 && need > 0) {
            int sfx = hist[tid];
            int nxt = (tid < 255) ? hist[tid + 1] : 0;
            if (sfx >= need && nxt < need) s_tb = tid;
        }
    }
    __syncthreads();
    const int tb = s_tb;

    for (int idx = tid; idx < NFG * TOPK; idx += 512) {
        int c20 = idx / TOPK, slot = idx % TOPK;
        if (slot < skc[c20]) {
            unsigned bits = __float_as_uint(g_kscore[(b * NFG + c20) * TOPK + slot]);
            unsigned bin = (bits - 0x3F000000u) >> 15;
            if (bin > 255u) bin = 255u;
            if ((int)bin >= tb) {
                int p = atomicAdd(&s_cnt, 1);
                if (p < GCAP)
                    buf[p] = ((unsigned long long)bits << 32) |
                             (0xFFFFFFFFu - (unsigned)(c20 * 256 + slot));
            }
        }
    }
    __syncthreads();
    int cnt = s_cnt; if (cnt > GCAP) cnt = GCAP;
    for (int i = cnt + tid; i < GCAP; i += 512) buf[i] = 0ull;

    for (unsigned k = 2; k <= GCAP; k <<= 1)
        for (unsigned j = k >> 1; j; j >>= 1) {
            __syncthreads();
            if (tid < GCAP / 2) {
                unsigned p = (unsigned)tid;
                unsigned i = ((p & ~(j - 1u)) << 1) | (p & (j - 1u));
                unsigned l = i | j;
                unsigned long long x = buf[i], y = buf[l];
                bool up = ((i & k) == 0u);
                if (up ? (x > y) : (x < y)) { buf[i] = y; buf[l] = x; }
            }
        }
    __syncthreads();

    if (tid < TOPK) {
        unsigned long long key = buf[GCAP - 1 - tid];
        float b0 = 0.f, b1 = 0.f, b2 = 0.f, b3 = 0.f, sco = 0.f, lab = 0.f;
        if ((key >> 32) != 0ull) {
            unsigned code = 0xFFFFFFFFu - (unsigned)(key & 0xFFFFFFFFu);
            int c20  = (int)(code >> 8);
            int slot = (int)(code & 255u);
            int base = (b * NFG + c20) * TOPK + slot;
            sco = __uint_as_float((unsigned)(key >> 32));
            b0 = g_kbox[base * 4 + 0];
            b1 = g_kbox[base * 4 + 1];
            b2 = g_kbox[base * 4 + 2];
            b3 = g_kbox[base * 4 + 3];
            lab = (float)(c20 + 1);
        }
        int r = tid;
        out[(b * TOPK + r) * 4 + 0] = b0;
        out[(b * TOPK + r) * 4 + 1] = b1;
        out[(b * TOPK + r) * 4 + 2] = b2;
        out[(b * TOPK + r) * 4 + 3] = b3;
        out[BATCH * TOPK * 4 + b * TOPK + r] = sco;
        out[BATCH * TOPK * 5 + b * TOPK + r] = lab;
    }
}

// ============================================================
extern "C" void kernel_launch(void* const* d_in, const int* in_sizes, int n_in,
                              void* d_out, int out_size) {
    const float* cls  = (const float*)d_in[0];  // [8, 8732, 21]
    const float* loc  = (const float*)d_in[1];  // [8, 8732, 4]
    const float* anch = (const float*)d_in[2];  // [8732, 4]
    float* out = (float*)d_out;

    prep_kernel<<<DEC_BLOCKS + TR_BLOCKS, 256>>>(cls, loc, anch);
    nms_kernel<<<BATCH * NFG, 512>>>();
    topk_kernel<<<BATCH, 512>>>(out);
}

// round 3
// speedup vs baseline: 1.2535x; 1.0146x over previous
#include <cuda_runtime.h>
#include <math.h>

#define BATCH   8
#define NA      8732
#define NC      21
#define NFG     20
#define TOPK    200
#define PRE     1024
#define CAND    2048
#define GCAP    512
#define CONF_T  0.5f
#define NMS_T   0.45f

// ---- scratch (static __device__, allocation-free) ----
__device__ float g_kscore[BATCH * NFG * TOPK];       // kept scores per (img, class)
__device__ float g_kbox[BATCH * NFG * TOPK * 4];     // kept boxes per (img, class)
__device__ int   g_kcount[BATCH * NFG];              // kept counts

// ============================================================
// Kernel 1: per-(image,class) top-1024 select + sort + greedy NMS.
// 512 threads/CTA, 2 CTAs/SM, 160 CTAs -> single wave.
// ============================================================
__global__ __launch_bounds__(512, 2) void nms_kernel(const float* __restrict__ cls,
                                                     const float* __restrict__ loc,
                                                     const float* __restrict__ anch) {
    const int bc  = blockIdx.x;
    const int b   = bc / NFG;
    const int c20 = bc % NFG;
    const int tid = threadIdx.x;

    __shared__ int hist[256];
    __shared__ unsigned long long cand[CAND];
    __shared__ float4 sbox[PRE];
    __shared__ float  sar[PRE], ssc[PRE];
    __shared__ unsigned aw[32];          // alive bitmap: word w = candidates [32w,32w+32)
    __shared__ int s_tb, s_cnt;

    if (tid < 256) hist[tid] = 0;
    if (tid == 0) { s_cnt = 0; s_tb = 256; }
    __syncthreads();

    // column of scores for (b, class c20+1), stride NC
    const float* scol = cls + (size_t)b * NA * NC + (c20 + 1);

    // ---- A: histogram over float-bit bins (monotone in score) ----
    for (int a = tid; a < NA; a += 512) {
        float s = scol[(size_t)a * NC];
        if (s > CONF_T) {
            unsigned bin = (__float_as_uint(s) - 0x3F000000u) >> 15;
            if (bin > 255u) bin = 255u;
            atomicAdd(&hist[bin], 1);
        }
    }
    __syncthreads();

    // ---- B: suffix scan; exact bit-threshold bin ----
    for (int off = 1; off < 256; off <<= 1) {
        int v = 0;
        if (tid < 256) v = (tid + off < 256) ? hist[tid + off] : 0;
        __syncthreads();
        if (tid < 256) hist[tid] += v;
        __syncthreads();
    }
    {
        int total = hist[0];
        int need = total < PRE ? total : PRE;
        if (tid < 256 && need > 0) {
            int sfx = hist[tid];
            int nxt = (tid < 255) ? hist[tid + 1] : 0;
            if (sfx >= need && nxt < need) s_tb = tid;
        }
    }
    __syncthreads();
    const int tb = s_tb;

    // ---- C: compact candidates above threshold bin ----
    for (int a = tid; a < NA; a += 512) {
        float s = scol[(size_t)a * NC];
        if (s > CONF_T) {
            unsigned bits = __float_as_uint(s);
            unsigned bin = (bits - 0x3F000000u) >> 15;
            if (bin > 255u) bin = 255u;
            if ((int)bin >= tb) {
                int p = atomicAdd(&s_cnt, 1);
                if (p < CAND)
                    cand[p] = ((unsigned long long)bits << 32) |
                              (unsigned)(65535 - a);
            }
        }
    }
    __syncthreads();
    int cnt = s_cnt; if (cnt > CAND) cnt = CAND;
    for (int i = cnt + tid; i < CAND; i += 512) cand[i] = 0ull;

    // ---- D: bitonic sort ascending, 2048 x u64, pair-indexed ----
    for (unsigned k = 2; k <= CAND; k <<= 1)
        for (unsigned j = k >> 1; j; j >>= 1) {
            __syncthreads();
            #pragma unroll
            for (int q = 0; q < 2; ++q) {
                unsigned p = (unsigned)tid + (unsigned)q * 512u;
                unsigned i = ((p & ~(j - 1u)) << 1) | (p & (j - 1u));
                unsigned l = i | j;
                unsigned long long x = cand[i], y = cand[l];
                bool up = ((i & k) == 0u);
                if (up ? (x > y) : (x < y)) { cand[i] = y; cand[l] = x; }
            }
        }
    __syncthreads();

    const int count = cnt < PRE ? cnt : PRE;

    // ---- E: decode candidate boxes on the fly (rank r best-first) ----
    const float4* loc4  = reinterpret_cast<const float4*>(loc);
    const float4* anch4 = reinterpret_cast<const float4*>(anch);
    float4 obox[2]; float oar[2]; int oalive[2];
    #pragma unroll
    for (int t = 0; t < 2; ++t) {
        int r = tid + t * 512;
        unsigned long long key = cand[CAND - 1 - r];
        if (r < count) {
            int a = 65535 - (int)(key & 0xFFFFu);
            float4 l  = loc4[b * NA + a];
            float4 an = anch4[a];
            float cx = an.x + l.x * 0.1f * an.z;
            float cy = an.y + l.y * 0.1f * an.w;
            float w  = an.z * expf(l.z * 0.2f);
            float h  = an.w * expf(l.w * 0.2f);
            float x1 = cx - w * 0.5f;
            float y1 = cy - h * 0.5f;
            float4 bb;
            bb.x = fminf(fmaxf(x1 * 300.0f, 0.0f), 299.0f);
            bb.y = fminf(fmaxf(y1 * 300.0f, 0.0f), 299.0f);
            bb.z = fminf(fmaxf((x1 + w) * 300.0f, 0.0f), 299.0f);
            bb.w = fminf(fmaxf((y1 + h) * 300.0f, 0.0f), 299.0f);
            float area = (bb.z - bb.x + 1.0f) * (bb.w - bb.y + 1.0f);
            sbox[r] = bb; sar[r] = area;
            ssc[r] = __uint_as_float((unsigned)(key >> 32));
            obox[t] = bb; oar[t] = area; oalive[t] = 1;
        } else {
            oalive[t] = 0;
        }
    }
    // alive bitmap init from count
    if (tid < 32) {
        int lo = tid * 32;
        unsigned w;
        if (count >= lo + 32)      w = 0xFFFFFFFFu;
        else if (count <= lo)      w = 0u;
        else                       w = (1u << (count - lo)) - 1u;
        aw[tid] = w;
    }

    // ---- F: greedy NMS, one block-wide turn per KEPT box ----
    int nkept = 0;
    int pos = 0;
    const int wid = tid >> 5;
    for (;;) {
        __syncthreads();                       // bitmap stable
        if (pos >= PRE) break;
        int w = pos >> 5;
        unsigned v = aw[w] & (0xFFFFFFFFu << (pos & 31));
        while (v == 0u && w < 31) { ++w; v = aw[w]; }
        if (v == 0u) break;                    // uniform: no alive left
        int i = (w << 5) + __ffs(v) - 1;
        float4 ib = sbox[i];
        float  ia = sar[i];
        if (tid == 0) {
            int base = bc * TOPK + nkept;
            g_kscore[base]       = ssc[i];
            g_kbox[base * 4 + 0] = ib.x;
            g_kbox[base * 4 + 1] = ib.y;
            g_kbox[base * 4 + 2] = ib.z;
            g_kbox[base * 4 + 3] = ib.w;
        }
        ++nkept;
        // suppress own candidates (r > i), clear the kept one
        #pragma unroll
        for (int t = 0; t < 2; ++t) {
            int r = tid + t * 512;
            if (oalive[t]) {
                if (r == i) oalive[t] = 0;
                else if (r > i) {
                    float4 bb = obox[t];
                    float xx1 = fmaxf(ib.x, bb.x), yy1 = fmaxf(ib.y, bb.y);
                    float xx2 = fminf(ib.z, bb.z), yy2 = fminf(ib.w, bb.w);
                    float ww = fmaxf(xx2 - xx1 + 1.0f, 0.0f);
                    float hh = fmaxf(yy2 - yy1 + 1.0f, 0.0f);
                    float inter = ww * hh;
                    float iou = inter / (ia + oar[t] - inter);
                    if (iou > NMS_T) oalive[t] = 0;
                }
            }
        }
        __syncthreads();                       // all reads of aw done
        unsigned b0 = __ballot_sync(0xFFFFFFFFu, oalive[0]);
        unsigned b1 = __ballot_sync(0xFFFFFFFFu, oalive[1]);
        if ((tid & 31) == 0) { aw[wid] = b0; aw[16 + wid] = b1; }
        if (nkept >= TOPK) break;
        pos = i + 1;
    }
    if (tid == 0) g_kcount[bc] = nkept;
}

// ============================================================
// Kernel 2: per-image global top-200 via bit-histogram threshold
// then 512-key bitonic sort. Exact tie-breaking preserved.
// ============================================================
__global__ __launch_bounds__(512) void topk_kernel(float* __restrict__ out) {
    const int b = blockIdx.x;
    const int tid = threadIdx.x;
    __shared__ int hist[256];
    __shared__ unsigned long long buf[GCAP];
    __shared__ int s_cnt, s_tb;
    __shared__ int skc[NFG];

    if (tid < 256) hist[tid] = 0;
    if (tid == 0) { s_cnt = 0; s_tb = 256; }
    if (tid < NFG) skc[tid] = g_kcount[b * NFG + tid];
    __syncthreads();

    for (int idx = tid; idx < NFG * TOPK; idx += 512) {
        int c20 = idx / TOPK, slot = idx % TOPK;
        if (slot < skc[c20]) {
            unsigned bits = __float_as_uint(g_kscore[(b * NFG + c20) * TOPK + slot]);
            unsigned bin = (bits - 0x3F000000u) >> 15;
            if (bin > 255u) bin = 255u;
            atomicAdd(&hist[bin], 1);
        }
    }
    __syncthreads();
    for (int off = 1; off < 256; off <<= 1) {
        int v = 0;
        if (tid < 256) v = (tid + off < 256) ? hist[tid + off] : 0;
        __syncthreads();
        if (tid < 256) hist[tid] += v;
        __syncthreads();
    }
    {
        int total = hist[0];
        int need = total < TOPK ? total : TOPK;
        if (tid < 256 && need > 0) {
            int sfx = hist[tid];
            int nxt = (tid < 255) ? hist[tid + 1] : 0;
            if (sfx >= need && nxt < need) s_tb = tid;
        }
    }
    __syncthreads();
    const int tb = s_tb;

    for (int idx = tid; idx < NFG * TOPK; idx += 512) {
        int c20 = idx / TOPK, slot = idx % TOPK;
        if (slot < skc[c20]) {
            unsigned bits = __float_as_uint(g_kscore[(b * NFG + c20) * TOPK + slot]);
            unsigned bin = (bits - 0x3F000000u) >> 15;
            if (bin > 255u) bin = 255u;
            if ((int)bin >= tb) {
                int p = atomicAdd(&s_cnt, 1);
                if (p < GCAP)
                    buf[p] = ((unsigned long long)bits << 32) |
                             (0xFFFFFFFFu - (unsigned)(c20 * 256 + slot));
            }
        }
    }
    __syncthreads();
    int cnt = s_cnt; if (cnt > GCAP) cnt = GCAP;
    for (int i = cnt + tid; i < GCAP; i += 512) buf[i] = 0ull;

    for (unsigned k = 2; k <= GCAP; k <<= 1)
        for (unsigned j = k >> 1; j; j >>= 1) {
            __syncthreads();
            if (tid < GCAP / 2) {
                unsigned p = (unsigned)tid;
                unsigned i = ((p & ~(j - 1u)) << 1) | (p & (j - 1u));
                unsigned l = i | j;
                unsigned long long x = buf[i], y = buf[l];
                bool up = ((i & k) == 0u);
                if (up ? (x > y) : (x < y)) { buf[i] = y; buf[l] = x; }
            }
        }
    __syncthreads();

    if (tid < TOPK) {
        unsigned long long key = buf[GCAP - 1 - tid];
        float b0 = 0.f, b1 = 0.f, b2 = 0.f, b3 = 0.f, sco = 0.f, lab = 0.f;
        if ((key >> 32) != 0ull) {
            unsigned code = 0xFFFFFFFFu - (unsigned)(key & 0xFFFFFFFFu);
            int c20  = (int)(code >> 8);
            int slot = (int)(code & 255u);
            int base = (b * NFG + c20) * TOPK + slot;
            sco = __uint_as_float((unsigned)(key >> 32));
            b0 = g_kbox[base * 4 + 0];
            b1 = g_kbox[base * 4 + 1];
            b2 = g_kbox[base * 4 + 2];
            b3 = g_kbox[base * 4 + 3];
            lab = (float)(c20 + 1);
        }
        int r = tid;
        out[(b * TOPK + r) * 4 + 0] = b0;
        out[(b * TOPK + r) * 4 + 1] = b1;
        out[(b * TOPK + r) * 4 + 2] = b2;
        out[(b * TOPK + r) * 4 + 3] = b3;
        out[BATCH * TOPK * 4 + b * TOPK + r] = sco;
        out[BATCH * TOPK * 5 + b * TOPK + r] = lab;
    }
}

// ============================================================
extern "C" void kernel_launch(void* const* d_in, const int* in_sizes, int n_in,
                              void* d_out, int out_size) {
    const float* cls  = (const float*)d_in[0];  // [8, 8732, 21]
    const float* loc  = (const float*)d_in[1];  // [8, 8732, 4]
    const float* anch = (const float*)d_in[2];  // [8732, 4]
    float* out = (float*)d_out;

    nms_kernel<<<BATCH * NFG, 512>>>(cls, loc, anch);
    topk_kernel<<<BATCH, 512>>>(out);
}

// round 4
// speedup vs baseline: 1.5221x; 1.2143x over previous
#include <cuda_runtime.h>
#include <math.h>

#define BATCH   8
#define NA      8732
#define NC      21
#define NFG     20
#define TOPK    200
#define PRE     1024
#define CAND    2048
#define GCAP    512
#define CONF_T  0.5f
#define NMS_T   0.45f
#define FULLM   0xFFFFFFFFu

// ---- scratch (static __device__, allocation-free) ----
__device__ float g_kscore[BATCH * NFG * TOPK];
__device__ float g_kbox[BATCH * NFG * TOPK * 4];
__device__ int   g_kcount[BATCH * NFG];

__device__ __forceinline__ bool iou_gt(float4 p, float pa, float4 q, float qa) {
    float xx1 = fmaxf(p.x, q.x), yy1 = fmaxf(p.y, q.y);
    float xx2 = fminf(p.z, q.z), yy2 = fminf(p.w, q.w);
    float w = fmaxf(xx2 - xx1 + 1.0f, 0.0f);
    float h = fmaxf(yy2 - yy1 + 1.0f, 0.0f);
    float inter = w * h;
    return inter / (pa + qa - inter) > NMS_T;
}

// warp0: suffix scan over 256-bin hist; pick largest bin tb with suffix>=need.
// Returns via s_tb. needCap = PRE or TOPK.
__device__ __forceinline__ void warp_suffix_threshold(int* hist, int needCap,
                                                      int* s_tb) {
    int lane = threadIdx.x;
    int h[8], s[8];
    int b8 = lane * 8;
#pragma unroll
    for (int q = 0; q < 8; ++q) h[q] = hist[b8 + q];
    s[7] = h[7];
#pragma unroll
    for (int q = 6; q >= 0; --q) s[q] = h[q] + s[q + 1];
    int T = s[0];
    int S = T;
#pragma unroll
    for (int off = 1; off < 32; off <<= 1) {
        int v = __shfl_down_sync(FULLM, S, off);
        if (lane + off < 32) S += v;
    }
    int total = __shfl_sync(FULLM, S, 0);
    int need = total < needCap ? total : needCap;
    int Sab = S - T;
    int best = -1;
    if (need > 0) {
#pragma unroll
        for (int q = 7; q >= 0; --q)
            if (s[q] + Sab >= need) { best = b8 + q; break; }
    }
#pragma unroll
    for (int off = 16; off; off >>= 1)
        best = max(best, __shfl_xor_sync(FULLM, best, off));
    if (lane == 0) *s_tb = (best < 0) ? 256 : best;
}

// ============================================================
// Kernel 1: per-(image,class) select + sort + tiled greedy NMS.
// ============================================================
__global__ __launch_bounds__(512, 2) void nms_kernel(const float* __restrict__ cls,
                                                     const float* __restrict__ loc,
                                                     const float* __restrict__ anch) {
    const int bc  = blockIdx.x;
    const int b   = bc / NFG;
    const int c20 = bc % NFG;
    const int tid = threadIdx.x;
    const int wid = tid >> 5;
    const int lane = tid & 31;

    __shared__ int hist[256];
    __shared__ unsigned long long cand[CAND];      // 16KB; reused in phase F
    __shared__ float4 sbox[PRE];
    __shared__ float  sar[PRE], ssc[PRE];
    __shared__ unsigned pf[8];
    __shared__ int s_tb, s_cnt, s_nL;

    // phase-F overlays of cand (dead after phase E)
    unsigned* mask = (unsigned*)cand;              // 256*8 u32 = 8KB
    float4*   lbox = (float4*)(cand + 1024);       // 200*16B
    float*    lar  = (float*)(cand + 1424);        // 200*4B

    if (tid < 256) hist[tid] = 0;
    if (tid == 0) { s_cnt = 0; s_tb = 256; s_nL = 0; }
    __syncthreads();

    const float* scol = cls + (size_t)b * NA * NC + (c20 + 1);

    // ---- A: load scores once into registers; histogram ----
    float sv[18];
#pragma unroll
    for (int k = 0; k < 18; ++k) {
        int a = tid + k * 512;
        float s = -1.0f;
        if (a < NA) s = scol[(size_t)a * NC];
        sv[k] = s;
        if (s > CONF_T) {
            unsigned bin = (__float_as_uint(s) - 0x3F000000u) >> 15;
            if (bin > 255u) bin = 255u;
            atomicAdd(&hist[bin], 1);
        }
    }
    __syncthreads();

    // ---- B: warp0 suffix scan -> threshold bin ----
    if (tid < 32) warp_suffix_threshold(hist, PRE, &s_tb);
    __syncthreads();
    const int tb = s_tb;

    // ---- C: compact from registers ----
#pragma unroll
    for (int k = 0; k < 18; ++k) {
        float s = sv[k];
        if (s > CONF_T) {
            unsigned bits = __float_as_uint(s);
            unsigned bin = (bits - 0x3F000000u) >> 15;
            if (bin > 255u) bin = 255u;
            if ((int)bin >= tb) {
                int p = atomicAdd(&s_cnt, 1);
                if (p < CAND) {
                    int a = tid + k * 512;
                    cand[p] = ((unsigned long long)bits << 32) |
                              (unsigned)(65535 - a);
                }
            }
        }
    }
    __syncthreads();
    int cnt = s_cnt; if (cnt > CAND) cnt = CAND;
    for (int i = cnt + tid; i < CAND; i += 512) cand[i] = 0ull;
    __syncthreads();

    // ---- D: bitonic sort asc; warp-local stages for j<=64 ----
    for (unsigned k = 2; k <= CAND; k <<= 1) {
        unsigned j = k >> 1;
        bool crossed = false;
        while (j >= 128) {
            __syncthreads();
#pragma unroll
            for (int q = 0; q < 2; ++q) {
                unsigned p = (unsigned)tid + (unsigned)q * 512u;
                unsigned i = ((p & ~(j - 1u)) << 1) | (p & (j - 1u));
                unsigned l = i | j;
                unsigned long long x = cand[i], y = cand[l];
                bool up = ((i & k) == 0u);
                if (up ? (x > y) : (x < y)) { cand[i] = y; cand[l] = x; }
            }
            j >>= 1;
            crossed = true;
        }
        if (crossed) __syncthreads();
        for (; j >= 1; j >>= 1) {
            __syncwarp();
#pragma unroll
            for (int t = 0; t < 2; ++t) {
                unsigned p = (unsigned)(wid * 64 + lane + 32 * t);
                unsigned i = ((p & ~(j - 1u)) << 1) | (p & (j - 1u));
                unsigned l = i | j;
                unsigned long long x = cand[i], y = cand[l];
                bool up = ((i & k) == 0u);
                if (up ? (x > y) : (x < y)) { cand[i] = y; cand[l] = x; }
            }
        }
    }
    __syncthreads();

    const int count = cnt < PRE ? cnt : PRE;

    // ---- E: decode candidate boxes best-first ----
    const float4* loc4  = reinterpret_cast<const float4*>(loc);
    const float4* anch4 = reinterpret_cast<const float4*>(anch);
#pragma unroll
    for (int t = 0; t < 2; ++t) {
        int r = tid + t * 512;
        if (r < count) {
            unsigned long long key = cand[CAND - 1 - r];
            int a = 65535 - (int)(key & 0xFFFFu);
            float4 l  = loc4[b * NA + a];
            float4 an = anch4[a];
            float cx = an.x + l.x * 0.1f * an.z;
            float cy = an.y + l.y * 0.1f * an.w;
            float w  = an.z * expf(l.z * 0.2f);
            float h  = an.w * expf(l.w * 0.2f);
            float x1 = cx - w * 0.5f;
            float y1 = cy - h * 0.5f;
            float4 bb;
            bb.x = fminf(fmaxf(x1 * 300.0f, 0.0f), 299.0f);
            bb.y = fminf(fmaxf(y1 * 300.0f, 0.0f), 299.0f);
            bb.z = fminf(fmaxf((x1 + w) * 300.0f, 0.0f), 299.0f);
            bb.w = fminf(fmaxf((y1 + h) * 300.0f, 0.0f), 299.0f);
            sbox[r] = bb;
            sar[r] = (bb.z - bb.x + 1.0f) * (bb.w - bb.y + 1.0f);
            ssc[r] = __uint_as_float((unsigned)(key >> 32));
        }
    }
    __syncthreads();   // cand dead; overlays live from here

    // ---- F: tiled greedy NMS (mask + single-thread scan) ----
    int nL = 0;
    for (int base = 0; base < count && nL < TOPK; base += 256) {
        int m = count - base; if (m > 256) m = 256;
        if (tid < 8) pf[tid] = 0u;
        __syncthreads();
        // prefilter vs kept list (2 threads per candidate)
        {
            int cl = tid >> 1, half = tid & 1;
            if (cl < m && nL > 0) {
                float4 bb = sbox[base + cl];
                float ab = sar[base + cl];
                bool dead = false;
                for (int kk = half; kk < nL; kk += 2)
                    if (iou_gt(lbox[kk], lar[kk], bb, ab)) { dead = true; break; }
                if (dead) atomicOr(&pf[cl >> 5], 1u << (cl & 31));
            }
        }
        // intra-tile triangular mask (independent of prefilter)
#pragma unroll
        for (int q = 0; q < 4; ++q) {
            int jid = tid + q * 512;
            int i = jid >> 3, w = jid & 7;
            if (i < m) {
                float4 bi = sbox[base + i];
                float ai = sar[base + i];
                unsigned bits = 0u;
                int j0 = w * 32;
                int jhi = m - j0; if (jhi > 32) jhi = 32;
                for (int l = 0; l < jhi; ++l) {
                    int j = j0 + l;
                    if (j > i && iou_gt(bi, ai, sbox[base + j], sar[base + j]))
                        bits |= 1u << l;
                }
                mask[i * 8 + w] = bits;
            }
        }
        __syncthreads();
        // serial greedy scan by one thread, all in registers
        if (tid == 0) {
            unsigned rm0 = pf[0], rm1 = pf[1], rm2 = pf[2], rm3 = pf[3];
            unsigned rm4 = pf[4], rm5 = pf[5], rm6 = pf[6], rm7 = pf[7];
            unsigned rv[8] = {rm0, rm1, rm2, rm3, rm4, rm5, rm6, rm7};
            int n = nL;
            for (int i = 0; i < m; ++i) {
                if (!((rv[i >> 5] >> (i & 31)) & 1u)) {
                    float4 bb = sbox[base + i];
                    lbox[n] = bb;
                    lar[n] = sar[base + i];
                    int gb = bc * TOPK + n;
                    g_kscore[gb] = ssc[base + i];
                    *reinterpret_cast<float4*>(&g_kbox[gb * 4]) = bb;
                    ++n;
                    if (n >= TOPK) break;
                    const unsigned* mr = &mask[i * 8];
#pragma unroll
                    for (int w = 0; w < 8; ++w) rv[w] |= mr[w];
                }
            }
            s_nL = n;
        }
        __syncthreads();
        nL = s_nL;
    }
    if (tid == 0) g_kcount[bc] = nL;
}

// ============================================================
// Kernel 2: per-image global top-200. 256 threads, warp-local bitonic.
// ============================================================
__global__ __launch_bounds__(256) void topk_kernel(float* __restrict__ out) {
    const int b = blockIdx.x;
    const int tid = threadIdx.x;
    const int wid = tid >> 5;
    const int lane = tid & 31;
    __shared__ int hist[256];
    __shared__ unsigned long long buf[GCAP];
    __shared__ int s_cnt, s_tb;
    __shared__ int skc[NFG];

    hist[tid] = 0;
    if (tid == 0) { s_cnt = 0; s_tb = 256; }
    if (tid < NFG) skc[tid] = g_kcount[b * NFG + tid];
    __syncthreads();

    for (int idx = tid; idx < NFG * TOPK; idx += 256) {
        int c20 = idx / TOPK, slot = idx - c20 * TOPK;
        if (slot < skc[c20]) {
            unsigned bits = __float_as_uint(g_kscore[(b * NFG + c20) * TOPK + slot]);
            unsigned bin = (bits - 0x3F000000u) >> 15;
            if (bin > 255u) bin = 255u;
            atomicAdd(&hist[bin], 1);
        }
    }
    __syncthreads();
    if (tid < 32) warp_suffix_threshold(hist, TOPK, &s_tb);
    __syncthreads();
    const int tb = s_tb;

    for (int idx = tid; idx < NFG * TOPK; idx += 256) {
        int c20 = idx / TOPK, slot = idx - c20 * TOPK;
        if (slot < skc[c20]) {
            unsigned bits = __float_as_uint(g_kscore[(b * NFG + c20) * TOPK + slot]);
            unsigned bin = (bits - 0x3F000000u) >> 15;
            if (bin > 255u) bin = 255u;
            if ((int)bin >= tb) {
                int p = atomicAdd(&s_cnt, 1);
                if (p < GCAP)
                    buf[p] = ((unsigned long long)bits << 32) |
                             (0xFFFFFFFFu - (unsigned)(c20 * 256 + slot));
            }
        }
    }
    __syncthreads();
    int cnt = s_cnt; if (cnt > GCAP) cnt = GCAP;
    for (int i = cnt + tid; i < GCAP; i += 256) buf[i] = 0ull;
    __syncthreads();

    // bitonic sort 512 keys; warp w owns [64w, 64w+64); j<=32 warp-local
    for (unsigned k = 2; k <= GCAP; k <<= 1) {
        unsigned j = k >> 1;
        bool crossed = false;
        while (j >= 64) {
            __syncthreads();
            unsigned p = (unsigned)tid;
            unsigned i = ((p & ~(j - 1u)) << 1) | (p & (j - 1u));
            unsigned l = i | j;
            unsigned long long x = buf[i], y = buf[l];
            bool up = ((i & k) == 0u);
            if (up ? (x > y) : (x < y)) { buf[i] = y; buf[l] = x; }
            j >>= 1;
            crossed = true;
        }
        if (crossed) __syncthreads();
        for (; j >= 1; j >>= 1) {
            __syncwarp();
            unsigned p = (unsigned)(wid * 32 + lane);
            unsigned i = ((p & ~(j - 1u)) << 1) | (p & (j - 1u));
            unsigned l = i | j;
            unsigned long long x = buf[i], y = buf[l];
            bool up = ((i & k) == 0u);
            if (up ? (x > y) : (x < y)) { buf[i] = y; buf[l] = x; }
        }
    }
    __syncthreads();

    if (tid < TOPK) {
        unsigned long long key = buf[GCAP - 1 - tid];
        float b0 = 0.f, b1 = 0.f, b2 = 0.f, b3 = 0.f, sco = 0.f, lab = 0.f;
        if ((key >> 32) != 0ull) {
            unsigned code = 0xFFFFFFFFu - (unsigned)(key & 0xFFFFFFFFu);
            int c20  = (int)(code >> 8);
            int slot = (int)(code & 255u);
            int base = (b * NFG + c20) * TOPK + slot;
            sco = __uint_as_float((unsigned)(key >> 32));
            b0 = g_kbox[base * 4 + 0];
            b1 = g_kbox[base * 4 + 1];
            b2 = g_kbox[base * 4 + 2];
            b3 = g_kbox[base * 4 + 3];
            lab = (float)(c20 + 1);
        }
        out[(b * TOPK + tid) * 4 + 0] = b0;
        out[(b * TOPK + tid) * 4 + 1] = b1;
        out[(b * TOPK + tid) * 4 + 2] = b2;
        out[(b * TOPK + tid) * 4 + 3] = b3;
        out[BATCH * TOPK * 4 + b * TOPK + tid] = sco;
        out[BATCH * TOPK * 5 + b * TOPK + tid] = lab;
    }
}

// ============================================================
extern "C" void kernel_launch(void* const* d_in, const int* in_sizes, int n_in,
                              void* d_out, int out_size) {
    const float* cls  = (const float*)d_in[0];  // [8, 8732, 21]
    const float* loc  = (const float*)d_in[1];  // [8, 8732, 4]
    const float* anch = (const float*)d_in[2];  // [8732, 4]
    float* out = (float*)d_out;

    nms_kernel<<<BATCH * NFG, 512>>>(cls, loc, anch);
    topk_kernel<<<BATCH, 256>>>(out);
}

// round 6
// speedup vs baseline: 1.5830x; 1.0400x over previous
#include <cuda_runtime.h>
#include <math.h>

#define BATCH   8
#define NA      8732
#define NC      21
#define NFG     20
#define TOPK    200
#define PRE     1024
#define DCAP    1280
#define FBINS   2048
#define FSH     12
#define BASEB   0x3F000000u
#define CONF_T  0.5f
#define NMS_T   0.45f
#define FULLM   0xFFFFFFFFu

// ---- scratch (static __device__, allocation-free) ----
__device__ float g_kscore[BATCH * NFG * TOPK];
__device__ float g_kbox[BATCH * NFG * TOPK * 4];
__device__ int   g_kcount[BATCH * NFG];

__device__ __forceinline__ bool iou_gt(float4 p, float pa, float4 q, float qa) {
    float xx1 = fmaxf(p.x, q.x), yy1 = fmaxf(p.y, q.y);
    float xx2 = fminf(p.z, q.z), yy2 = fminf(p.w, q.w);
    float w = fmaxf(xx2 - xx1 + 1.0f, 0.0f);
    float h = fmaxf(yy2 - yy1 + 1.0f, 0.0f);
    float inter = w * h;
    return inter / (pa + qa - inter) > NMS_T;
}

__device__ __forceinline__ unsigned finebin(unsigned bits) {
    unsigned fb = (bits - BASEB) >> FSH;
    return fb > (FBINS - 1u) ? (FBINS - 1u) : fb;
}

// Block suffix-scan over FBINS bins (512 threads, 4 consecutive bins each).
// On exit: hist[fb] = suffix[fb+1] (scatter cursor / bin start),
// sfx[q] = suffix including own bin. Returns total.
__device__ __forceinline__ int suffix_scan_2048(int* hist, int tid, int* sfx) {
    __shared__ int ws[16];
    __shared__ int s_total;
    const int lane = tid & 31, wid = tid >> 5;
    int b4 = tid * 4;
    int h0 = hist[b4], h1 = hist[b4 + 1], h2 = hist[b4 + 2], h3 = hist[b4 + 3];
    sfx[3] = h3; sfx[2] = h2 + sfx[3]; sfx[1] = h1 + sfx[2]; sfx[0] = h0 + sfx[1];
    int T = sfx[0], S = T;
#pragma unroll
    for (int off = 1; off < 32; off <<= 1) {
        int v = __shfl_down_sync(FULLM, S, off);
        if (lane + off < 32) S += v;
    }
    if (lane == 0) ws[wid] = S;
    __syncthreads();
    if (tid < 16) {
        int W = ws[tid];
#pragma unroll
        for (int off = 1; off < 16; off <<= 1) {
            int v = __shfl_down_sync(0x0000FFFFu, W, off);
            if (tid + off < 16) W += v;
        }
        ws[tid] = W;
        if (tid == 0) s_total = W;
    }
    __syncthreads();
    int above = ((wid < 15) ? ws[wid + 1] : 0) + (S - T);
    sfx[0] += above; sfx[1] += above; sfx[2] += above; sfx[3] += above;
    hist[b4]     = sfx[1];
    hist[b4 + 1] = sfx[2];
    hist[b4 + 2] = sfx[3];
    hist[b4 + 3] = above;
    return s_total;
}

// ============================================================
// Kernel 1: per-(image,class) bucket top-1024 + fixpoint greedy NMS.
// ============================================================
__global__ __launch_bounds__(512, 2) void nms_kernel(const float* __restrict__ cls,
                                                     const float* __restrict__ loc,
                                                     const float* __restrict__ anch) {
    const int bc  = blockIdx.x;
    const int b   = bc / NFG;
    const int c20 = bc % NFG;
    const int tid = threadIdx.x;

    __shared__ int histbuf[FBINS];                   // 8KB: hist, then colmask
    __shared__ unsigned long long dest[DCAP];        // 10KB: keys, then lbox/lar
    __shared__ float4 sbox[PRE];                     // 16KB
    __shared__ float  sar[PRE], ssc[PRE];            // 8KB
    __shared__ unsigned kw[8], pf[8];
    __shared__ int psum[8];
    __shared__ int s_ftb, s_sel, s_flag;

    int* hist = histbuf;                             // phases A-C
    unsigned* colmask = (unsigned*)histbuf;          // phase F (256*8 u32 = 8KB)
    float4* lbox = (float4*)dest;                    // phase F
    float*  lar  = (float*)(dest + 512);             // phase F

    for (int i = tid; i < FBINS; i += 512) hist[i] = 0;
    if (tid == 0) { s_ftb = -1; s_sel = 0; }
    __syncthreads();

    const float* scol = cls + (size_t)b * NA * NC + (c20 + 1);

    // ---- A: fine histogram over score bits ----
    for (int a = tid; a < NA; a += 512) {
        float s = scol[(size_t)a * NC];
        if (s > CONF_T) atomicAdd(&hist[finebin(__float_as_uint(s))], 1);
    }
    __syncthreads();

    // ---- B: suffix scan -> threshold fine-bin + cursors ----
    int sfx[4];
    int total = suffix_scan_2048(hist, tid, sfx);
    int need = total < PRE ? total : PRE;
    if (need > 0) {
        int local = -1;
#pragma unroll
        for (int q = 3; q >= 0; --q)
            if (sfx[q] >= need) { local = tid * 4 + q; break; }
        if (local >= 0) atomicMax(&s_ftb, local);
    }
    __syncthreads();
    const int ftb = s_ftb;
    if (ftb >= 0 && (ftb >> 2) == tid) s_sel = sfx[ftb & 3];
    __syncthreads();
    int count = s_sel; if (count > PRE) count = PRE; if (count > DCAP) count = DCAP;

    // ---- C: scatter candidates to exact positions + per-bin tie sort ----
    if (ftb >= 0) {
        for (int a = tid; a < NA; a += 512) {
            float s = scol[(size_t)a * NC];
            if (s > CONF_T) {
                unsigned bits = __float_as_uint(s);
                int fb = (int)finebin(bits);
                if (fb >= ftb) {
                    int pos = atomicAdd(&hist[fb], 1);
                    if (pos < DCAP)
                        dest[pos] = ((unsigned long long)bits << 32) |
                                    (unsigned)(65535 - a);
                }
            }
        }
        __syncthreads();
        for (int fb = ftb + tid; fb < FBINS; fb += 512) {
            int lo = (fb == FBINS - 1) ? 0 : hist[fb + 1];
            int hi = hist[fb];
            if (hi > DCAP) hi = DCAP;
            if (lo > hi) lo = hi;
            for (int x = lo + 1; x < hi; ++x) {
                unsigned long long key = dest[x];
                int y = x - 1;
                while (y >= lo && dest[y] < key) { dest[y + 1] = dest[y]; --y; }
                dest[y + 1] = key;
            }
        }
        __syncthreads();
    }

    // ---- E: decode candidate boxes best-first ----
    const float4* loc4  = reinterpret_cast<const float4*>(loc);
    const float4* anch4 = reinterpret_cast<const float4*>(anch);
#pragma unroll
    for (int t = 0; t < 2; ++t) {
        int r = tid + t * 512;
        if (r < count) {
            unsigned long long key = dest[r];
            int a = 65535 - (int)(key & 0xFFFFu);
            float4 l  = loc4[b * NA + a];
            float4 an = anch4[a];
            float cx = an.x + l.x * 0.1f * an.z;
            float cy = an.y + l.y * 0.1f * an.w;
            float w  = an.z * expf(l.z * 0.2f);
            float h  = an.w * expf(l.w * 0.2f);
            float x1 = cx - w * 0.5f;
            float y1 = cy - h * 0.5f;
            float4 bb;
            bb.x = fminf(fmaxf(x1 * 300.0f, 0.0f), 299.0f);
            bb.y = fminf(fmaxf(y1 * 300.0f, 0.0f), 299.0f);
            bb.z = fminf(fmaxf((x1 + w) * 300.0f, 0.0f), 299.0f);
            bb.w = fminf(fmaxf((y1 + h) * 300.0f, 0.0f), 299.0f);
            sbox[r] = bb;
            sar[r] = (bb.z - bb.x + 1.0f) * (bb.w - bb.y + 1.0f);
            ssc[r] = __uint_as_float((unsigned)(key >> 32));
        }
    }
    __syncthreads();   // hist & dest dead; colmask/lbox/lar overlays live

    // ---- F: tiled greedy NMS via parallel fixpoint ----
    int nL = 0;
    for (int base = 0; base < count && nL < TOPK; base += 256) {
        int m = count - base; if (m > 256) m = 256;
        if (tid < 8) pf[tid] = 0u;
        __syncthreads();
        if (base > 0 && nL > 0) {        // prefilter vs already-kept boxes
            int i = tid >> 1, half = tid & 1;
            if (i < m) {
                float4 bb = sbox[base + i];
                float ab = sar[base + i];
                bool dead = false;
                for (int k = half; k < nL; k += 2)
                    if (iou_gt(lbox[k], lar[k], bb, ab)) { dead = true; break; }
                if (dead) atomicOr(&pf[i >> 5], 1u << (i & 31));
            }
        }
        // triangular IoU mask: colmask[i][w] = bits j in [32w,32w+32), j<i
#pragma unroll
        for (int q = 0; q < 4; ++q) {
            int jid = tid + q * 512;
            int i = jid >> 3, w = jid & 7;
            if (i < m) {
                float4 bi = sbox[base + i];
                float ai = sar[base + i];
                unsigned bits = 0u;
                int j0 = w * 32;
                int jn = i - j0; if (jn > 32) jn = 32;
                for (int l = 0; l < jn; ++l)
                    if (iou_gt(bi, ai, sbox[base + j0 + l], sar[base + j0 + l]))
                        bits |= 1u << l;
                colmask[i * 8 + w] = bits;
            }
        }
        __syncthreads();
        if (tid < 8) {
            int lo = tid * 32;
            unsigned valid;
            if (m >= lo + 32)      valid = FULLM;
            else if (m <= lo)      valid = 0u;
            else                   valid = (1u << (m - lo)) - 1u;
            kw[tid] = valid & ~pf[tid];
        }
        __syncthreads();
        // fixpoint: K[i] = pre_alive[i] && no kept j<i with iou>T
        for (;;) {
            if (tid == 0) s_flag = 0;
            int alive = 0;
            if (tid < m && !((pf[tid >> 5] >> (tid & 31)) & 1u)) {
                unsigned acc = 0u;
#pragma unroll
                for (int w = 0; w < 8; ++w) acc |= colmask[tid * 8 + w] & kw[w];
                alive = (acc == 0u);
            }
            __syncthreads();
            unsigned nw = __ballot_sync(FULLM, alive);
            if (tid < 256 && (tid & 31) == 0) {
                if (nw != kw[tid >> 5]) s_flag = 1;
                kw[tid >> 5] = nw;
            }
            __syncthreads();
            if (!s_flag) break;
        }
        // extraction: parallel ranked writes
        if (tid < 8) {
            int s = 0;
            for (int w2 = 0; w2 < tid; ++w2) s += __popc(kw[w2]);
            psum[tid] = s;
        }
        __syncthreads();
        int nk = psum[7] + __popc(kw[7]);
        int take = TOPK - nL; if (take > nk) take = nk;
        if (tid < m && ((kw[tid >> 5] >> (tid & 31)) & 1u)) {
            int r = psum[tid >> 5] + __popc(kw[tid >> 5] & ((1u << (tid & 31)) - 1u));
            if (r < take) {
                int slot = nL + r;
                int gb = bc * TOPK + slot;
                g_kscore[gb] = ssc[base + tid];
                *reinterpret_cast<float4*>(&g_kbox[gb * 4]) = sbox[base + tid];
                lbox[slot] = sbox[base + tid];
                lar[slot]  = sar[base + tid];
            }
        }
        nL += take;
        __syncthreads();
    }
    if (tid == 0) g_kcount[bc] = nL;
}

// ============================================================
// Kernel 2: per-image global top-200 via bucket scatter.
// ============================================================
__global__ __launch_bounds__(512) void topk_kernel(float* __restrict__ out) {
    const int b = blockIdx.x;
    const int tid = threadIdx.x;
    __shared__ int hist[FBINS];
    __shared__ unsigned long long dest[512];
    __shared__ int skc[NFG];
    __shared__ int s_ftb, s_sel;

    for (int i = tid; i < FBINS; i += 512) hist[i] = 0;
    if (tid == 0) { s_ftb = -1; s_sel = 0; }
    if (tid < NFG) skc[tid] = g_kcount[b * NFG + tid];
    __syncthreads();

    for (int idx = tid; idx < NFG * TOPK; idx += 512) {
        int c20 = idx / TOPK, slot = idx - c20 * TOPK;
        if (slot < skc[c20]) {
            unsigned bits = __float_as_uint(g_kscore[(b * NFG + c20) * TOPK + slot]);
            atomicAdd(&hist[finebin(bits)], 1);
        }
    }
    __syncthreads();

    int sfx[4];
    int total = suffix_scan_2048(hist, tid, sfx);
    int need = total < TOPK ? total : TOPK;
    if (need > 0) {
        int local = -1;
#pragma unroll
        for (int q = 3; q >= 0; --q)
            if (sfx[q] >= need) { local = tid * 4 + q; break; }
        if (local >= 0) atomicMax(&s_ftb, local);
    }
    __syncthreads();
    const int ftb = s_ftb;
    if (ftb >= 0 && (ftb >> 2) == tid) s_sel = sfx[ftb & 3];
    __syncthreads();
    int count = s_sel; if (count > TOPK) count = TOPK; if (count > 512) count = 512;

    if (ftb >= 0) {
        for (int idx = tid; idx < NFG * TOPK; idx += 512) {
            int c20 = idx / TOPK, slot = idx - c20 * TOPK;
            if (slot < skc[c20]) {
                unsigned bits = __float_as_uint(g_kscore[(b * NFG + c20) * TOPK + slot]);
                int fb = (int)finebin(bits);
                if (fb >= ftb) {
                    int pos = atomicAdd(&hist[fb], 1);
                    if (pos < 512)
                        dest[pos] = ((unsigned long long)bits << 32) |
                                    (0xFFFFFFFFu - (unsigned)(c20 * 256 + slot));
                }
            }
        }
        __syncthreads();
        for (int fb = ftb + tid; fb < FBINS; fb += 512) {
            int lo = (fb == FBINS - 1) ? 0 : hist[fb + 1];
            int hi = hist[fb];
            if (hi > 512) hi = 512;
            if (lo > hi) lo = hi;
            for (int x = lo + 1; x < hi; ++x) {
                unsigned long long key = dest[x];
                int y = x - 1;
                while (y >= lo && dest[y] < key) { dest[y + 1] = dest[y]; --y; }
                dest[y + 1] = key;
            }
        }
        __syncthreads();
    }

    if (tid < TOPK) {
        float b0 = 0.f, b1 = 0.f, b2 = 0.f, b3 = 0.f, sco = 0.f, lab = 0.f;
        if (tid < count) {
            unsigned long long key = dest[tid];
            unsigned code = 0xFFFFFFFFu - (unsigned)(key & 0xFFFFFFFFu);
            int c20  = (int)(code >> 8);
            int slot = (int)(code & 255u);
            int base = (b * NFG + c20) * TOPK + slot;
            sco = __uint_as_float((unsigned)(key >> 32));
            b0 = g_kbox[base * 4 + 0];
            b1 = g_kbox[base * 4 + 1];
            b2 = g_kbox[base * 4 + 2];
            b3 = g_kbox[base * 4 + 3];
            lab = (float)(c20 + 1);
        }
        out[(b * TOPK + tid) * 4 + 0] = b0;
        out[(b * TOPK + tid) * 4 + 1] = b1;
        out[(b * TOPK + tid) * 4 + 2] = b2;
        out[(b * TOPK + tid) * 4 + 3] = b3;
        out[BATCH * TOPK * 4 + b * TOPK + tid] = sco;
        out[BATCH * TOPK * 5 + b * TOPK + tid] = lab;
    }
}

// ============================================================
extern "C" void kernel_launch(void* const* d_in, const int* in_sizes, int n_in,
                              void* d_out, int out_size) {
    const float* cls  = (const float*)d_in[0];  // [8, 8732, 21]
    const float* loc  = (const float*)d_in[1];  // [8, 8732, 4]
    const float* anch = (const float*)d_in[2];  // [8732, 4]
    float* out = (float*)d_out;

    nms_kernel<<<BATCH * NFG, 512>>>(cls, loc, anch);
    topk_kernel<<<BATCH, 512>>>(out);
}

// round 8
// speedup vs baseline: 1.6014x; 1.0116x over previous
#include <cuda_runtime.h>
#include <math.h>

#define BATCH   8
#define NA      8732
#define NAP     8736
#define NC      21
#define NFG     20
#define TOPK    200
#define PRE     1024
#define DCAP    1280
#define FBINS   2048
#define FSH     12
#define BASEB   0x3F000000u
#define CONF_T  0.5f
#define NMS_T   0.45f
#define FULLM   0xFFFFFFFFu

// ---- scratch (static __device__, allocation-free) ----
__device__ float    g_clsT[BATCH * NFG * NAP];   // transposed scores [b][c][a]
__device__ float    g_kscore[BATCH * NFG * TOPK];
__device__ float4   g_kbox[BATCH * NFG * TOPK];  // natively 16B-aligned
__device__ int      g_kcount[BATCH * NFG];
__device__ unsigned g_done[BATCH];               // wrap counters (stay 0 after each run)

#define TR_TILE   128
#define TR_TPB    ((NA + TR_TILE - 1) / TR_TILE)   // 69
#define TR_BLOCKS (BATCH * TR_TPB)

__device__ __forceinline__ bool iou_gt(float4 p, float pa, float4 q, float qa) {
    float xx1 = fmaxf(p.x, q.x), yy1 = fmaxf(p.y, q.y);
    float xx2 = fminf(p.z, q.z), yy2 = fminf(p.w, q.w);
    float w = fmaxf(xx2 - xx1 + 1.0f, 0.0f);
    float h = fmaxf(yy2 - yy1 + 1.0f, 0.0f);
    float inter = w * h;
    return inter / (pa + qa - inter) > NMS_T;
}

__device__ __forceinline__ unsigned finebin(unsigned bits) {
    unsigned fb = (bits - BASEB) >> FSH;
    return fb > (FBINS - 1u) ? (FBINS - 1u) : fb;
}

// Block suffix-scan over FBINS bins (512 threads, 4 consecutive bins each).
// On exit: hist[fb] = suffix[fb+1] (scatter cursor / bin start),
// sfx[q] = suffix including own bin; *above_out = suffix of bin b4+4.
// Returns total.
__device__ __forceinline__ int suffix_scan_2048(int* hist, int tid, int* sfx,
                                                int* above_out) {
    __shared__ int ws[16];
    __shared__ int s_total;
    const int lane = tid & 31, wid = tid >> 5;
    int b4 = tid * 4;
    int h0 = hist[b4], h1 = hist[b4 + 1], h2 = hist[b4 + 2], h3 = hist[b4 + 3];
    sfx[3] = h3; sfx[2] = h2 + sfx[3]; sfx[1] = h1 + sfx[2]; sfx[0] = h0 + sfx[1];
    int T = sfx[0], S = T;
#pragma unroll
    for (int off = 1; off < 32; off <<= 1) {
        int v = __shfl_down_sync(FULLM, S, off);
        if (lane + off < 32) S += v;
    }
    if (lane == 0) ws[wid] = S;
    __syncthreads();
    if (tid < 16) {
        int W = ws[tid];
#pragma unroll
        for (int off = 1; off < 16; off <<= 1) {
            int v = __shfl_down_sync(0x0000FFFFu, W, off);
            if (tid + off < 16) W += v;
        }
        ws[tid] = W;
        if (tid == 0) s_total = W;
    }
    __syncthreads();
    int above = ((wid < 15) ? ws[wid + 1] : 0) + (S - T);
    sfx[0] += above; sfx[1] += above; sfx[2] += above; sfx[3] += above;
    hist[b4]     = sfx[1];
    hist[b4 + 1] = sfx[2];
    hist[b4 + 2] = sfx[3];
    hist[b4 + 3] = above;
    *above_out = above;
    return s_total;
}

// ============================================================
// Kernel 1: transpose cls [b][a][c] -> g_clsT [b][c][a] (coalesced).
// ============================================================
__global__ void prep_kernel(const float* __restrict__ cls) {
    __shared__ float sh[TR_TILE * NC];
    int t = blockIdx.x;
    int b = t / TR_TPB, tile = t % TR_TPB;
    int a0 = tile * TR_TILE;
    int n = NA - a0; if (n > TR_TILE) n = TR_TILE;
    const float* src = cls + ((size_t)(b * NA + a0)) * NC;
    for (int i = threadIdx.x; i < n * NC; i += 256) sh[i] = src[i];
    __syncthreads();
    int half = threadIdx.x >> 7;       // 0: classes 0..9, 1: classes 10..19
    int t2 = threadIdx.x & 127;
    if (t2 < n) {
        for (int c = half * 10; c < half * 10 + 10; ++c)
            g_clsT[((size_t)(b * NFG + c)) * NAP + a0 + t2] = sh[t2 * NC + c + 1];
    }
}

// ============================================================
// Kernel 2: bucket top-1024 + fixpoint greedy NMS; last CTA per image
// also performs the per-image global top-200 (fused).
// ============================================================
__global__ __launch_bounds__(512, 2) void nms_kernel(const float* __restrict__ loc,
                                                     const float* __restrict__ anch,
                                                     float* __restrict__ out) {
    const int bc  = blockIdx.x;
    const int b   = bc / NFG;
    const int c20 = bc % NFG;
    const int tid = threadIdx.x;

    __shared__ __align__(16) int histbuf[FBINS];             // 8KB
    __shared__ __align__(16) unsigned long long dest[DCAP];  // 10KB
    __shared__ __align__(16) float4 sbox[PRE];               // 16KB
    __shared__ float  sar[PRE], ssc[PRE];                    // 8KB
    __shared__ unsigned kw[8], pf[8];
    __shared__ int psum[8];
    __shared__ int skc[NFG];
    __shared__ int s_ftb, s_sel, s_flag, s_last;

    int* hist = histbuf;
    unsigned* colmask = (unsigned*)histbuf;          // phase F (256*8 u32)
    float4* lbox = (float4*)dest;                    // phase F (16B-aligned now)
    float*  lar  = (float*)(dest + 512);             // phase F

    for (int i = tid; i < FBINS; i += 512) hist[i] = 0;
    if (tid == 0) { s_ftb = -1; s_sel = 0; }
    __syncthreads();

    const float* scol = g_clsT + ((size_t)(b * NFG + c20)) * NAP;

    // ---- A: fine histogram (coalesced reads) ----
    for (int a = tid; a < NA; a += 512) {
        float s = scol[a];
        if (s > CONF_T) atomicAdd(&hist[finebin(__float_as_uint(s))], 1);
    }
    __syncthreads();

    // ---- B: suffix scan; unique-boundary threshold (no atomics) ----
    int sfx[4], above;
    int total = suffix_scan_2048(hist, tid, sfx, &above);
    {
        int need = total < PRE ? total : PRE;
        if (need > 0) {
#pragma unroll
            for (int q = 0; q < 4; ++q) {
                int nxt = (q < 3) ? sfx[q + 1] : above;
                if (sfx[q] >= need && nxt < need) {
                    s_ftb = tid * 4 + q;            // unique writer
                    s_sel = sfx[q];
                }
            }
        }
    }
    __syncthreads();
    const int ftb = s_ftb;
    int count = s_sel; if (count > PRE) count = PRE; if (count > DCAP) count = DCAP;

    // ---- C: scatter to exact positions + per-bin tie sort ----
    if (ftb >= 0) {
        for (int a = tid; a < NA; a += 512) {
            float s = scol[a];
            if (s > CONF_T) {
                unsigned bits = __float_as_uint(s);
                int fb = (int)finebin(bits);
                if (fb >= ftb) {
                    int pos = atomicAdd(&hist[fb], 1);
                    if (pos < DCAP)
                        dest[pos] = ((unsigned long long)bits << 32) |
                                    (unsigned)(65535 - a);
                }
            }
        }
        __syncthreads();
        for (int fb = ftb + tid; fb < FBINS; fb += 512) {
            int lo = (fb == FBINS - 1) ? 0 : hist[fb + 1];
            int hi = hist[fb];
            if (hi > DCAP) hi = DCAP;
            if (lo > hi) lo = hi;
            for (int x = lo + 1; x < hi; ++x) {
                unsigned long long key = dest[x];
                int y = x - 1;
                while (y >= lo && dest[y] < key) { dest[y + 1] = dest[y]; --y; }
                dest[y + 1] = key;
            }
        }
        __syncthreads();
    }

    // ---- E: decode candidate boxes best-first ----
    const float4* loc4  = reinterpret_cast<const float4*>(loc);
    const float4* anch4 = reinterpret_cast<const float4*>(anch);
#pragma unroll
    for (int t = 0; t < 2; ++t) {
        int r = tid + t * 512;
        if (r < count) {
            unsigned long long key = dest[r];
            int a = 65535 - (int)(key & 0xFFFFu);
            float4 l  = loc4[b * NA + a];
            float4 an = anch4[a];
            float cx = an.x + l.x * 0.1f * an.z;
            float cy = an.y + l.y * 0.1f * an.w;
            float w  = an.z * expf(l.z * 0.2f);
            float h  = an.w * expf(l.w * 0.2f);
            float x1 = cx - w * 0.5f;
            float y1 = cy - h * 0.5f;
            float4 bb;
            bb.x = fminf(fmaxf(x1 * 300.0f, 0.0f), 299.0f);
            bb.y = fminf(fmaxf(y1 * 300.0f, 0.0f), 299.0f);
            bb.z = fminf(fmaxf((x1 + w) * 300.0f, 0.0f), 299.0f);
            bb.w = fminf(fmaxf((y1 + h) * 300.0f, 0.0f), 299.0f);
            sbox[r] = bb;
            sar[r] = (bb.z - bb.x + 1.0f) * (bb.w - bb.y + 1.0f);
            ssc[r] = __uint_as_float((unsigned)(key >> 32));
        }
    }
    __syncthreads();   // hist & dest dead; overlays live

    // ---- F: tiled greedy NMS via parallel fixpoint ----
    int nL = 0;
    for (int base = 0; base < count && nL < TOPK; base += 256) {
        int m = count - base; if (m > 256) m = 256;
        if (tid < 8) pf[tid] = 0u;
        __syncthreads();
        if (base > 0 && nL > 0) {
            int i = tid >> 1, half = tid & 1;
            if (i < m) {
                float4 bb = sbox[base + i];
                float ab = sar[base + i];
                bool dead = false;
                for (int k = half; k < nL; k += 2)
                    if (iou_gt(lbox[k], lar[k], bb, ab)) { dead = true; break; }
                if (dead) atomicOr(&pf[i >> 5], 1u << (i & 31));
            }
        }
#pragma unroll
        for (int q = 0; q < 4; ++q) {
            int jid = tid + q * 512;
            int i = jid >> 3, w = jid & 7;
            if (i < m) {
                float4 bi = sbox[base + i];
                float ai = sar[base + i];
                unsigned bits = 0u;
                int j0 = w * 32;
                int jn = i - j0; if (jn > 32) jn = 32;
                for (int l = 0; l < jn; ++l)
                    if (iou_gt(bi, ai, sbox[base + j0 + l], sar[base + j0 + l]))
                        bits |= 1u << l;
                colmask[i * 8 + w] = bits;
            }
        }
        __syncthreads();
        if (tid < 8) {
            int lo = tid * 32;
            unsigned valid;
            if (m >= lo + 32)      valid = FULLM;
            else if (m <= lo)      valid = 0u;
            else                   valid = (1u << (m - lo)) - 1u;
            kw[tid] = valid & ~pf[tid];
        }
        __syncthreads();
        for (;;) {
            if (tid == 0) s_flag = 0;
            int alive = 0;
            if (tid < m && !((pf[tid >> 5] >> (tid & 31)) & 1u)) {
                unsigned acc = 0u;
#pragma unroll
                for (int w = 0; w < 8; ++w) acc |= colmask[tid * 8 + w] & kw[w];
                alive = (acc == 0u);
            }
            __syncthreads();
            unsigned nw = __ballot_sync(FULLM, alive);
            if (tid < 256 && (tid & 31) == 0) {
                if (nw != kw[tid >> 5]) s_flag = 1;
                kw[tid >> 5] = nw;
            }
            __syncthreads();
            int done = !s_flag;
            __syncthreads();           // all read s_flag before it is re-zeroed
            if (done) break;
        }
        if (tid < 8) {
            int s = 0;
            for (int w2 = 0; w2 < tid; ++w2) s += __popc(kw[w2]);
            psum[tid] = s;
        }
        __syncthreads();
        int nk = psum[7] + __popc(kw[7]);
        int take = TOPK - nL; if (take > nk) take = nk;
        if (tid < m && ((kw[tid >> 5] >> (tid & 31)) & 1u)) {
            int r = psum[tid >> 5] + __popc(kw[tid >> 5] & ((1u << (tid & 31)) - 1u));
            if (r < take) {
                int slot = nL + r;
                int gb = bc * TOPK + slot;
                g_kscore[gb] = ssc[base + tid];
                g_kbox[gb]   = sbox[base + tid];
                lbox[slot]   = sbox[base + tid];
                lar[slot]    = sar[base + tid];
            }
        }
        nL += take;
        __syncthreads();
    }
    if (tid == 0) g_kcount[bc] = nL;

    // ---- G: completion counter; last CTA of image runs the global top-200 ----
    if (tid == 0) {
        __threadfence();
        unsigned old = atomicInc(&g_done[b], NFG - 1);   // wraps to 0 at NFG
        s_last = (old == NFG - 1);
    }
    __syncthreads();
    if (!s_last) return;
    __threadfence();

    // ---- H: per-image global top-200 (bucket) ----
    for (int i = tid; i < FBINS; i += 512) hist[i] = 0;
    if (tid == 0) { s_ftb = -1; s_sel = 0; }
    if (tid < NFG) skc[tid] = g_kcount[b * NFG + tid];
    __syncthreads();

    for (int idx = tid; idx < NFG * TOPK; idx += 512) {
        int c = idx / TOPK, slot = idx - c * TOPK;
        if (slot < skc[c]) {
            unsigned bits = __float_as_uint(g_kscore[(b * NFG + c) * TOPK + slot]);
            atomicAdd(&hist[finebin(bits)], 1);
        }
    }
    __syncthreads();

    int total2 = suffix_scan_2048(hist, tid, sfx, &above);
    {
        int need = total2 < TOPK ? total2 : TOPK;
        if (need > 0) {
#pragma unroll
            for (int q = 0; q < 4; ++q) {
                int nxt = (q < 3) ? sfx[q + 1] : above;
                if (sfx[q] >= need && nxt < need) {
                    s_ftb = tid * 4 + q;
                    s_sel = sfx[q];
                }
            }
        }
    }
    __syncthreads();
    const int ftb2 = s_ftb;
    int count2 = s_sel; if (count2 > TOPK) count2 = TOPK; if (count2 > 512) count2 = 512;

    if (ftb2 >= 0) {
        for (int idx = tid; idx < NFG * TOPK; idx += 512) {
            int c = idx / TOPK, slot = idx - c * TOPK;
            if (slot < skc[c]) {
                unsigned bits = __float_as_uint(g_kscore[(b * NFG + c) * TOPK + slot]);
                int fb = (int)finebin(bits);
                if (fb >= ftb2) {
                    int pos = atomicAdd(&hist[fb], 1);
                    if (pos < 512)
                        dest[pos] = ((unsigned long long)bits << 32) |
                                    (0xFFFFFFFFu - (unsigned)(c * 256 + slot));
                }
            }
        }
        __syncthreads();
        for (int fb = ftb2 + tid; fb < FBINS; fb += 512) {
            int lo = (fb == FBINS - 1) ? 0 : hist[fb + 1];
            int hi = hist[fb];
            if (hi > 512) hi = 512;
            if (lo > hi) lo = hi;
            for (int x = lo + 1; x < hi; ++x) {
                unsigned long long key = dest[x];
                int y = x - 1;
                while (y >= lo && dest[y] < key) { dest[y + 1] = dest[y]; --y; }
                dest[y + 1] = key;
            }
        }
        __syncthreads();
    }

    if (tid < TOPK) {
        float b0 = 0.f, b1 = 0.f, b2 = 0.f, b3 = 0.f, sco = 0.f, lab = 0.f;
        if (tid < count2) {
            unsigned long long key = dest[tid];
            unsigned code = 0xFFFFFFFFu - (unsigned)(key & 0xFFFFFFFFu);
            int c    = (int)(code >> 8);
            int slot = (int)(code & 255u);
            float4 kb = g_kbox[(b * NFG + c) * TOPK + slot];
            sco = __uint_as_float((unsigned)(key >> 32));
            b0 = kb.x; b1 = kb.y; b2 = kb.z; b3 = kb.w;
            lab = (float)(c + 1);
        }
        out[(b * TOPK + tid) * 4 + 0] = b0;
        out[(b * TOPK + tid) * 4 + 1] = b1;
        out[(b * TOPK + tid) * 4 + 2] = b2;
        out[(b * TOPK + tid) * 4 + 3] = b3;
        out[BATCH * TOPK * 4 + b * TOPK + tid] = sco;
        out[BATCH * TOPK * 5 + b * TOPK + tid] = lab;
    }
}

// ============================================================
extern "C" void kernel_launch(void* const* d_in, const int* in_sizes, int n_in,
                              void* d_out, int out_size) {
    const float* cls  = (const float*)d_in[0];  // [8, 8732, 21]
    const float* loc  = (const float*)d_in[1];  // [8, 8732, 4]
    const float* anch = (const float*)d_in[2];  // [8732, 4]
    float* out = (float*)d_out;

    prep_kernel<<<TR_BLOCKS, 256>>>(cls);
    nms_kernel<<<BATCH * NFG, 512>>>(loc, anch, out);
}

// round 9
// speedup vs baseline: 1.7733x; 1.1074x over previous
#include <cuda_runtime.h>
#include <math.h>

#define BATCH   8
#define NA      8732
#define NAP     8736
#define NC      21
#define NFG     20
#define TOPK    200
#define PRE     1024
#define DCAP    1280
#define FBINS   2048
#define FSH     12
#define BASEB   0x3F000000u
#define CONF_T  0.5f
#define NMS_T   0.45f
#define FULLM   0xFFFFFFFFu

// ---- scratch (static __device__, allocation-free) ----
__device__ float    g_clsT[BATCH * NFG * NAP];   // transposed scores [b][c][a]; pad stays 0
__device__ float    g_kscore[BATCH * NFG * TOPK];
__device__ float4   g_kbox[BATCH * NFG * TOPK];
__device__ int      g_kcount[BATCH * NFG];
__device__ unsigned g_done[BATCH];               // wrap counters (stay 0 after each run)

#define TR_TILE   128
#define TR_TPB    ((NA + TR_TILE - 1) / TR_TILE)   // 69
#define TR_BLOCKS (BATCH * TR_TPB)

// exact same result as the clamped-form IoU test, with early-outs:
// if w<=0 or h<=0 the original gives inter=0 -> iou=0 -> false.
__device__ __forceinline__ bool iou_gt(float4 p, float pa, float4 q, float qa) {
    float w = fminf(p.z, q.z) - fmaxf(p.x, q.x) + 1.0f;
    if (w <= 0.0f) return false;
    float h = fminf(p.w, q.w) - fmaxf(p.y, q.y) + 1.0f;
    if (h <= 0.0f) return false;
    float inter = w * h;
    return inter / (pa + qa - inter) > NMS_T;   // identical operand order / IEEE div
}

__device__ __forceinline__ unsigned finebin(unsigned bits) {
    unsigned fb = (bits - BASEB) >> FSH;
    return fb > (FBINS - 1u) ? (FBINS - 1u) : fb;
}

// Block suffix-scan over FBINS bins (512 threads, 4 consecutive bins each).
__device__ __forceinline__ int suffix_scan_2048(int* hist, int tid, int* sfx,
                                                int* above_out) {
    __shared__ int ws[16];
    __shared__ int s_total;
    const int lane = tid & 31, wid = tid >> 5;
    int b4 = tid * 4;
    int h0 = hist[b4], h1 = hist[b4 + 1], h2 = hist[b4 + 2], h3 = hist[b4 + 3];
    sfx[3] = h3; sfx[2] = h2 + sfx[3]; sfx[1] = h1 + sfx[2]; sfx[0] = h0 + sfx[1];
    int T = sfx[0], S = T;
#pragma unroll
    for (int off = 1; off < 32; off <<= 1) {
        int v = __shfl_down_sync(FULLM, S, off);
        if (lane + off < 32) S += v;
    }
    if (lane == 0) ws[wid] = S;
    __syncthreads();
    if (tid < 16) {
        int W = ws[tid];
#pragma unroll
        for (int off = 1; off < 16; off <<= 1) {
            int v = __shfl_down_sync(0x0000FFFFu, W, off);
            if (tid + off < 16) W += v;
        }
        ws[tid] = W;
        if (tid == 0) s_total = W;
    }
    __syncthreads();
    int above = ((wid < 15) ? ws[wid + 1] : 0) + (S - T);
    sfx[0] += above; sfx[1] += above; sfx[2] += above; sfx[3] += above;
    hist[b4]     = sfx[1];
    hist[b4 + 1] = sfx[2];
    hist[b4 + 2] = sfx[3];
    hist[b4 + 3] = above;
    *above_out = above;
    return s_total;
}

// ============================================================
// Kernel 1: transpose cls [b][a][c] -> g_clsT [b][c][a] (coalesced).
// ============================================================
__global__ void prep_kernel(const float* __restrict__ cls) {
    __shared__ float sh[TR_TILE * NC];
    int t = blockIdx.x;
    int b = t / TR_TPB, tile = t % TR_TPB;
    int a0 = tile * TR_TILE;
    int n = NA - a0; if (n > TR_TILE) n = TR_TILE;
    const float* src = cls + ((size_t)(b * NA + a0)) * NC;
    for (int i = threadIdx.x; i < n * NC; i += 256) sh[i] = src[i];
    __syncthreads();
    int half = threadIdx.x >> 7;
    int t2 = threadIdx.x & 127;
    if (t2 < n) {
        for (int c = half * 10; c < half * 10 + 10; ++c)
            g_clsT[((size_t)(b * NFG + c)) * NAP + a0 + t2] = sh[t2 * NC + c + 1];
    }
}

// ============================================================
// Kernel 2: bucket top-1024 + fixpoint greedy NMS; last CTA per image
// also performs the per-image global top-200 (fused).
// ============================================================
__global__ __launch_bounds__(512, 2) void nms_kernel(const float* __restrict__ loc,
                                                     const float* __restrict__ anch,
                                                     float* __restrict__ out) {
    const int bc  = blockIdx.x;
    const int b   = bc / NFG;
    const int c20 = bc % NFG;
    const int tid = threadIdx.x;

    __shared__ __align__(16) int histbuf[FBINS];             // 8KB
    __shared__ __align__(16) unsigned long long dest[DCAP];  // 10KB
    __shared__ __align__(16) float4 sbox[PRE];               // 16KB
    __shared__ float  sar[PRE], ssc[PRE];                    // 8KB
    __shared__ unsigned kw[8], pf[8];
    __shared__ int psum[8];
    __shared__ int skc[NFG];
    __shared__ int s_ftb, s_sel, s_flag, s_last;

    int* hist = histbuf;
    unsigned* colmask = (unsigned*)histbuf;
    float4* lbox = (float4*)dest;
    float*  lar  = (float*)(dest + 512);

    for (int i = tid; i < FBINS; i += 512) hist[i] = 0;
    if (tid == 0) { s_ftb = -1; s_sel = 0; }
    __syncthreads();

    const float4* scol4 = reinterpret_cast<const float4*>(
        g_clsT + ((size_t)(b * NFG + c20)) * NAP);

    // ---- A: fine histogram, vectorized float4 (pad scores are 0) ----
    for (int v = tid; v < NAP / 4; v += 512) {
        float4 s4 = scol4[v];
        if (s4.x > CONF_T) atomicAdd(&hist[finebin(__float_as_uint(s4.x))], 1);
        if (s4.y > CONF_T) atomicAdd(&hist[finebin(__float_as_uint(s4.y))], 1);
        if (s4.z > CONF_T) atomicAdd(&hist[finebin(__float_as_uint(s4.z))], 1);
        if (s4.w > CONF_T) atomicAdd(&hist[finebin(__float_as_uint(s4.w))], 1);
    }
    __syncthreads();

    // ---- B: suffix scan; unique-boundary threshold (no atomics) ----
    int sfx[4], above;
    int total = suffix_scan_2048(hist, tid, sfx, &above);
    {
        int need = total < PRE ? total : PRE;
        if (need > 0) {
#pragma unroll
            for (int q = 0; q < 4; ++q) {
                int nxt = (q < 3) ? sfx[q + 1] : above;
                if (sfx[q] >= need && nxt < need) {
                    s_ftb = tid * 4 + q;
                    s_sel = sfx[q];
                }
            }
        }
    }
    __syncthreads();
    const int ftb = s_ftb;
    int count = s_sel; if (count > PRE) count = PRE; if (count > DCAP) count = DCAP;

    // ---- C: scatter to exact positions (vectorized) + per-bin tie sort ----
    if (ftb >= 0) {
        for (int v = tid; v < NAP / 4; v += 512) {
            float4 s4 = scol4[v];
            float sv[4] = {s4.x, s4.y, s4.z, s4.w};
#pragma unroll
            for (int k = 0; k < 4; ++k) {
                if (sv[k] > CONF_T) {
                    unsigned bits = __float_as_uint(sv[k]);
                    int fb = (int)finebin(bits);
                    if (fb >= ftb) {
                        int pos = atomicAdd(&hist[fb], 1);
                        if (pos < DCAP)
                            dest[pos] = ((unsigned long long)bits << 32) |
                                        (unsigned)(65535 - (4 * v + k));
                    }
                }
            }
        }
        __syncthreads();
        for (int fb = ftb + tid; fb < FBINS; fb += 512) {
            int lo = (fb == FBINS - 1) ? 0 : hist[fb + 1];
            int hi = hist[fb];
            if (hi > DCAP) hi = DCAP;
            if (lo > hi) lo = hi;
            for (int x = lo + 1; x < hi; ++x) {
                unsigned long long key = dest[x];
                int y = x - 1;
                while (y >= lo && dest[y] < key) { dest[y + 1] = dest[y]; --y; }
                dest[y + 1] = key;
            }
        }
        __syncthreads();
    }

    // ---- E: decode candidate boxes best-first ----
    const float4* loc4  = reinterpret_cast<const float4*>(loc);
    const float4* anch4 = reinterpret_cast<const float4*>(anch);
#pragma unroll
    for (int t = 0; t < 2; ++t) {
        int r = tid + t * 512;
        if (r < count) {
            unsigned long long key = dest[r];
            int a = 65535 - (int)(key & 0xFFFFu);
            float4 l  = loc4[b * NA + a];
            float4 an = anch4[a];
            float cx = an.x + l.x * 0.1f * an.z;
            float cy = an.y + l.y * 0.1f * an.w;
            float w  = an.z * expf(l.z * 0.2f);
            float h  = an.w * expf(l.w * 0.2f);
            float x1 = cx - w * 0.5f;
            float y1 = cy - h * 0.5f;
            float4 bb;
            bb.x = fminf(fmaxf(x1 * 300.0f, 0.0f), 299.0f);
            bb.y = fminf(fmaxf(y1 * 300.0f, 0.0f), 299.0f);
            bb.z = fminf(fmaxf((x1 + w) * 300.0f, 0.0f), 299.0f);
            bb.w = fminf(fmaxf((y1 + h) * 300.0f, 0.0f), 299.0f);
            sbox[r] = bb;
            sar[r] = (bb.z - bb.x + 1.0f) * (bb.w - bb.y + 1.0f);
            ssc[r] = __uint_as_float((unsigned)(key >> 32));
        }
    }
    __syncthreads();

    // ---- F: tiled greedy NMS via parallel fixpoint ----
    int nL = 0;
    for (int base = 0; base < count && nL < TOPK; base += 256) {
        int m = count - base; if (m > 256) m = 256;
        if (tid < 8) pf[tid] = 0u;
        __syncthreads();
        if (base > 0 && nL > 0) {
            int i = tid >> 1, half = tid & 1;
            if (i < m) {
                float4 bb = sbox[base + i];
                float ab = sar[base + i];
                bool dead = false;
                for (int k = half; k < nL; k += 2)
                    if (iou_gt(lbox[k], lar[k], bb, ab)) { dead = true; break; }
                if (dead) atomicOr(&pf[i >> 5], 1u << (i & 31));
            }
        }
        // triangular IoU mask with early-out (bit-identical decisions)
#pragma unroll
        for (int q = 0; q < 4; ++q) {
            int jid = tid + q * 512;
            int i = jid >> 3, w = jid & 7;
            if (i < m) {
                float4 bi = sbox[base + i];
                float ai = sar[base + i];
                unsigned bits = 0u;
                int j0 = base + w * 32;
                int jn = i - w * 32; if (jn > 32) jn = 32;
                if (jn == 32) {
#pragma unroll 8
                    for (int l = 0; l < 32; ++l) {
                        float4 bj = sbox[j0 + l];
                        float ww = fminf(bi.z, bj.z) - fmaxf(bi.x, bj.x) + 1.0f;
                        if (ww > 0.0f) {
                            float hh = fminf(bi.w, bj.w) - fmaxf(bi.y, bj.y) + 1.0f;
                            if (hh > 0.0f) {
                                float inter = ww * hh;
                                if (inter / (ai + sar[j0 + l] - inter) > NMS_T)
                                    bits |= 1u << l;
                            }
                        }
                    }
                } else {
                    for (int l = 0; l < jn; ++l) {
                        float4 bj = sbox[j0 + l];
                        float ww = fminf(bi.z, bj.z) - fmaxf(bi.x, bj.x) + 1.0f;
                        if (ww > 0.0f) {
                            float hh = fminf(bi.w, bj.w) - fmaxf(bi.y, bj.y) + 1.0f;
                            if (hh > 0.0f) {
                                float inter = ww * hh;
                                if (inter / (ai + sar[j0 + l] - inter) > NMS_T)
                                    bits |= 1u << l;
                            }
                        }
                    }
                }
                colmask[i * 8 + w] = bits;
            }
        }
        __syncthreads();
        if (tid < 8) {
            int lo = tid * 32;
            unsigned valid;
            if (m >= lo + 32)      valid = FULLM;
            else if (m <= lo)      valid = 0u;
            else                   valid = (1u << (m - lo)) - 1u;
            kw[tid] = valid & ~pf[tid];
        }
        __syncthreads();
        for (;;) {
            if (tid == 0) s_flag = 0;
            int alive = 0;
            if (tid < m && !((pf[tid >> 5] >> (tid & 31)) & 1u)) {
                unsigned acc = 0u;
#pragma unroll
                for (int w = 0; w < 8; ++w) acc |= colmask[tid * 8 + w] & kw[w];
                alive = (acc == 0u);
            }
            __syncthreads();
            unsigned nw = __ballot_sync(FULLM, alive);
            if (tid < 256 && (tid & 31) == 0) {
                if (nw != kw[tid >> 5]) s_flag = 1;
                kw[tid >> 5] = nw;
            }
            __syncthreads();
            int done = !s_flag;
            __syncthreads();
            if (done) break;
        }
        if (tid < 8) {
            int s = 0;
            for (int w2 = 0; w2 < tid; ++w2) s += __popc(kw[w2]);
            psum[tid] = s;
        }
        __syncthreads();
        int nk = psum[7] + __popc(kw[7]);
        int take = TOPK - nL; if (take > nk) take = nk;
        if (tid < m && ((kw[tid >> 5] >> (tid & 31)) & 1u)) {
            int r = psum[tid >> 5] + __popc(kw[tid >> 5] & ((1u << (tid & 31)) - 1u));
            if (r < take) {
                int slot = nL + r;
                int gb = bc * TOPK + slot;
                g_kscore[gb] = ssc[base + tid];
                g_kbox[gb]   = sbox[base + tid];
                lbox[slot]   = sbox[base + tid];
                lar[slot]    = sar[base + tid];
            }
        }
        nL += take;
        __syncthreads();
    }
    if (tid == 0) g_kcount[bc] = nL;

    // ---- G: completion counter; last CTA of image runs the global top-200 ----
    if (tid == 0) {
        __threadfence();
        unsigned old = atomicInc(&g_done[b], NFG - 1);
        s_last = (old == NFG - 1);
    }
    __syncthreads();
    if (!s_last) return;
    __threadfence();

    // ---- H: per-image global top-200 (bucket) ----
    for (int i = tid; i < FBINS; i += 512) hist[i] = 0;
    if (tid == 0) { s_ftb = -1; s_sel = 0; }
    if (tid < NFG) skc[tid] = g_kcount[b * NFG + tid];
    __syncthreads();

    for (int idx = tid; idx < NFG * TOPK; idx += 512) {
        int c = idx / TOPK, slot = idx - c * TOPK;
        if (slot < skc[c]) {
            unsigned bits = __float_as_uint(g_kscore[(b * NFG + c) * TOPK + slot]);
            atomicAdd(&hist[finebin(bits)], 1);
        }
    }
    __syncthreads();

    int total2 = suffix_scan_2048(hist, tid, sfx, &above);
    {
        int need = total2 < TOPK ? total2 : TOPK;
        if (need > 0) {
#pragma unroll
            for (int q = 0; q < 4; ++q) {
                int nxt = (q < 3) ? sfx[q + 1] : above;
                if (sfx[q] >= need && nxt < need) {
                    s_ftb = tid * 4 + q;
                    s_sel = sfx[q];
                }
            }
        }
    }
    __syncthreads();
    const int ftb2 = s_ftb;
    int count2 = s_sel; if (count2 > TOPK) count2 = TOPK; if (count2 > 512) count2 = 512;

    if (ftb2 >= 0) {
        for (int idx = tid; idx < NFG * TOPK; idx += 512) {
            int c = idx / TOPK, slot = idx - c * TOPK;
            if (slot < skc[c]) {
                unsigned bits = __float_as_uint(g_kscore[(b * NFG + c) * TOPK + slot]);
                int fb = (int)finebin(bits);
                if (fb >= ftb2) {
                    int pos = atomicAdd(&hist[fb], 1);
                    if (pos < 512)
                        dest[pos] = ((unsigned long long)bits << 32) |
                                    (0xFFFFFFFFu - (unsigned)(c * 256 + slot));
                }
            }
        }
        __syncthreads();
        for (int fb = ftb2 + tid; fb < FBINS; fb += 512) {
            int lo = (fb == FBINS - 1) ? 0 : hist[fb + 1];
            int hi = hist[fb];
            if (hi > 512) hi = 512;
            if (lo > hi) lo = hi;
            for (int x = lo + 1; x < hi; ++x) {
                unsigned long long key = dest[x];
                int y = x - 1;
                while (y >= lo && dest[y] < key) { dest[y + 1] = dest[y]; --y; }
                dest[y + 1] = key;
            }
        }
        __syncthreads();
    }

    if (tid < TOPK) {
        float b0 = 0.f, b1 = 0.f, b2 = 0.f, b3 = 0.f, sco = 0.f, lab = 0.f;
        if (tid < count2) {
            unsigned long long key = dest[tid];
            unsigned code = 0xFFFFFFFFu - (unsigned)(key & 0xFFFFFFFFu);
            int c    = (int)(code >> 8);
            int slot = (int)(code & 255u);
            float4 kb = g_kbox[(b * NFG + c) * TOPK + slot];
            sco = __uint_as_float((unsigned)(key >> 32));
            b0 = kb.x; b1 = kb.y; b2 = kb.z; b3 = kb.w;
            lab = (float)(c + 1);
        }
        out[(b * TOPK + tid) * 4 + 0] = b0;
        out[(b * TOPK + tid) * 4 + 1] = b1;
        out[(b * TOPK + tid) * 4 + 2] = b2;
        out[(b * TOPK + tid) * 4 + 3] = b3;
        out[BATCH * TOPK * 4 + b * TOPK + tid] = sco;
        out[BATCH * TOPK * 5 + b * TOPK + tid] = lab;
    }
}

// ============================================================
extern "C" void kernel_launch(void* const* d_in, const int* in_sizes, int n_in,
                              void* d_out, int out_size) {
    const float* cls  = (const float*)d_in[0];  // [8, 8732, 21]
    const float* loc  = (const float*)d_in[1];  // [8, 8732, 4]
    const float* anch = (const float*)d_in[2];  // [8732, 4]
    float* out = (float*)d_out;

    prep_kernel<<<TR_BLOCKS, 256>>>(cls);
    nms_kernel<<<BATCH * NFG, 512>>>(loc, anch, out);
}

// round 10
// speedup vs baseline: 2.3134x; 1.3046x over previous
#include <cuda_runtime.h>
#include <math.h>

#define BATCH   8
#define NA      8732
#define NAP     8736
#define NC      21
#define NFG     20
#define TOPK    200
#define PRE     1024
#define DCAP    1280
#define FBINS   2048
#define FSH     12
#define BASEB   0x3F000000u
#define CONF_T  0.5f
#define NMS_T   0.45f
#define FULLM   0xFFFFFFFFu

// ---- scratch (static __device__, allocation-free) ----
__device__ float    g_clsT[BATCH * NFG * NAP];   // transposed scores; pad stays 0
__device__ float    g_kscore[BATCH * NFG * TOPK];
__device__ float4   g_kbox[BATCH * NFG * TOPK];
__device__ int      g_kcount[BATCH * NFG];
__device__ unsigned g_done[BATCH];               // wrap counters (stay 0 after run)

#define TR_TILE   128
#define TR_TPB    ((NA + TR_TILE - 1) / TR_TILE)   // 69
#define TR_BLOCKS (BATCH * TR_TPB)

// exact same result as the clamped-form IoU test, with early-outs:
// if w<=0 or h<=0 the original gives inter=0 -> iou=0 -> false.
__device__ __forceinline__ bool iou_gt(float4 p, float pa, float4 q, float qa) {
    float w = fminf(p.z, q.z) - fmaxf(p.x, q.x) + 1.0f;
    if (w <= 0.0f) return false;
    float h = fminf(p.w, q.w) - fmaxf(p.y, q.y) + 1.0f;
    if (h <= 0.0f) return false;
    float inter = w * h;
    return inter / (pa + qa - inter) > NMS_T;   // identical operand order / IEEE div
}

__device__ __forceinline__ unsigned finebin(unsigned bits) {
    unsigned fb = (bits - BASEB) >> FSH;
    return fb > (FBINS - 1u) ? (FBINS - 1u) : fb;
}

// Block suffix-scan over FBINS bins (512 threads, 4 consecutive bins each).
__device__ __forceinline__ int suffix_scan_2048(int* hist, int tid, int* sfx,
                                                int* above_out) {
    __shared__ int ws[16];
    __shared__ int s_total;
    const int lane = tid & 31, wid = tid >> 5;
    int b4 = tid * 4;
    int h0 = hist[b4], h1 = hist[b4 + 1], h2 = hist[b4 + 2], h3 = hist[b4 + 3];
    sfx[3] = h3; sfx[2] = h2 + sfx[3]; sfx[1] = h1 + sfx[2]; sfx[0] = h0 + sfx[1];
    int T = sfx[0], S = T;
#pragma unroll
    for (int off = 1; off < 32; off <<= 1) {
        int v = __shfl_down_sync(FULLM, S, off);
        if (lane + off < 32) S += v;
    }
    if (lane == 0) ws[wid] = S;
    __syncthreads();
    if (tid < 16) {
        int W = ws[tid];
#pragma unroll
        for (int off = 1; off < 16; off <<= 1) {
            int v = __shfl_down_sync(0x0000FFFFu, W, off);
            if (tid + off < 16) W += v;
        }
        ws[tid] = W;
        if (tid == 0) s_total = W;
    }
    __syncthreads();
    int above = ((wid < 15) ? ws[wid + 1] : 0) + (S - T);
    sfx[0] += above; sfx[1] += above; sfx[2] += above; sfx[3] += above;
    hist[b4]     = sfx[1];
    hist[b4 + 1] = sfx[2];
    hist[b4 + 2] = sfx[3];
    hist[b4 + 3] = above;
    *above_out = above;
    return s_total;
}

// ============================================================
// Kernel 1: transpose cls [b][a][c] -> g_clsT [b][c][a] (coalesced).
// ============================================================
__global__ void prep_kernel(const float* __restrict__ cls) {
    __shared__ float sh[TR_TILE * NC];
    int t = blockIdx.x;
    int b = t / TR_TPB, tile = t % TR_TPB;
    int a0 = tile * TR_TILE;
    int n = NA - a0; if (n > TR_TILE) n = TR_TILE;
    const float* src = cls + ((size_t)(b * NA + a0)) * NC;
    for (int i = threadIdx.x; i < n * NC; i += 256) sh[i] = src[i];
    __syncthreads();
    int half = threadIdx.x >> 7;
    int t2 = threadIdx.x & 127;
    if (t2 < n) {
        for (int c = half * 10; c < half * 10 + 10; ++c)
            g_clsT[((size_t)(b * NFG + c)) * NAP + a0 + t2] = sh[t2 * NC + c + 1];
    }
}

// ============================================================
// Kernel 2: bucket top-1024 + fixpoint greedy NMS; last CTA per image
// also performs the per-image global top-200 (fused).
// ============================================================
__global__ __launch_bounds__(512, 2) void nms_kernel(const float* __restrict__ loc,
                                                     const float* __restrict__ anch,
                                                     float* __restrict__ out) {
    const int bc  = blockIdx.x;
    const int b   = bc / NFG;
    const int c20 = bc % NFG;
    const int tid = threadIdx.x;

    __shared__ __align__(16) int histbuf[FBINS];             // 8KB
    __shared__ __align__(16) unsigned long long dest[DCAP];  // 10KB
    __shared__ __align__(16) float4 sbox[PRE];               // 16KB
    __shared__ float  sar[PRE], ssc[PRE];                    // 8KB
    __shared__ unsigned kw[8], pf[8];
    __shared__ int psum[8];
    __shared__ int skc[NFG];
    __shared__ int s_ftb, s_sel, s_flag, s_last;

    int* hist = histbuf;
    unsigned* colmask = (unsigned*)histbuf;
    float4* lbox = (float4*)dest;
    float*  lar  = (float*)(dest + 512);

    for (int i = tid; i < FBINS; i += 512) hist[i] = 0;
    if (tid == 0) { s_ftb = -1; s_sel = 0; }
    __syncthreads();

    const float4* scol4 = reinterpret_cast<const float4*>(
        g_clsT + ((size_t)(b * NFG + c20)) * NAP);

    // ---- A: fine histogram, vectorized float4 (pad scores are 0) ----
    for (int v = tid; v < NAP / 4; v += 512) {
        float4 s4 = scol4[v];
        if (s4.x > CONF_T) atomicAdd(&hist[finebin(__float_as_uint(s4.x))], 1);
        if (s4.y > CONF_T) atomicAdd(&hist[finebin(__float_as_uint(s4.y))], 1);
        if (s4.z > CONF_T) atomicAdd(&hist[finebin(__float_as_uint(s4.z))], 1);
        if (s4.w > CONF_T) atomicAdd(&hist[finebin(__float_as_uint(s4.w))], 1);
    }
    __syncthreads();

    // ---- B: suffix scan; unique-boundary threshold (no atomics) ----
    int sfx[4], above;
    int total = suffix_scan_2048(hist, tid, sfx, &above);
    {
        int need = total < PRE ? total : PRE;
        if (need > 0) {
#pragma unroll
            for (int q = 0; q < 4; ++q) {
                int nxt = (q < 3) ? sfx[q + 1] : above;
                if (sfx[q] >= need && nxt < need) {
                    s_ftb = tid * 4 + q;
                    s_sel = sfx[q];
                }
            }
        }
    }
    __syncthreads();
    const int ftb = s_ftb;
    int count = s_sel; if (count > PRE) count = PRE; if (count > DCAP) count = DCAP;

    // ---- C: scatter to exact positions + per-bin tie sort ----
    if (ftb >= 0) {
        for (int v = tid; v < NAP / 4; v += 512) {
            float4 s4 = scol4[v];
            float sv[4] = {s4.x, s4.y, s4.z, s4.w};
#pragma unroll
            for (int k = 0; k < 4; ++k) {
                if (sv[k] > CONF_T) {
                    unsigned bits = __float_as_uint(sv[k]);
                    int fb = (int)finebin(bits);
                    if (fb >= ftb) {
                        int pos = atomicAdd(&hist[fb], 1);
                        if (pos < DCAP)
                            dest[pos] = ((unsigned long long)bits << 32) |
                                        (unsigned)(65535 - (4 * v + k));
                    }
                }
            }
        }
        __syncthreads();
        for (int fb = ftb + tid; fb < FBINS; fb += 512) {
            int lo = (fb == FBINS - 1) ? 0 : hist[fb + 1];
            int hi = hist[fb];
            if (hi > DCAP) hi = DCAP;
            if (lo > hi) lo = hi;
            for (int x = lo + 1; x < hi; ++x) {
                unsigned long long key = dest[x];
                int y = x - 1;
                while (y >= lo && dest[y] < key) { dest[y + 1] = dest[y]; --y; }
                dest[y + 1] = key;
            }
        }
        __syncthreads();
    }

    // ---- E: decode candidate boxes best-first ----
    const float4* loc4  = reinterpret_cast<const float4*>(loc);
    const float4* anch4 = reinterpret_cast<const float4*>(anch);
#pragma unroll
    for (int t = 0; t < 2; ++t) {
        int r = tid + t * 512;
        if (r < count) {
            unsigned long long key = dest[r];
            int a = 65535 - (int)(key & 0xFFFFu);
            float4 l  = loc4[b * NA + a];
            float4 an = anch4[a];
            float cx = an.x + l.x * 0.1f * an.z;
            float cy = an.y + l.y * 0.1f * an.w;
            float w  = an.z * expf(l.z * 0.2f);
            float h  = an.w * expf(l.w * 0.2f);
            float x1 = cx - w * 0.5f;
            float y1 = cy - h * 0.5f;
            float4 bb;
            bb.x = fminf(fmaxf(x1 * 300.0f, 0.0f), 299.0f);
            bb.y = fminf(fmaxf(y1 * 300.0f, 0.0f), 299.0f);
            bb.z = fminf(fmaxf((x1 + w) * 300.0f, 0.0f), 299.0f);
            bb.w = fminf(fmaxf((y1 + h) * 300.0f, 0.0f), 299.0f);
            sbox[r] = bb;
            sar[r] = (bb.z - bb.x + 1.0f) * (bb.w - bb.y + 1.0f);
            ssc[r] = __uint_as_float((unsigned)(key >> 32));
        }
    }
    __syncthreads();

    // ---- F: tiled greedy NMS via parallel fixpoint ----
    int nL = 0;
    for (int base = 0; base < count && nL < TOPK; base += 256) {
        int m = count - base; if (m > 256) m = 256;
        if (tid < 8) pf[tid] = 0u;
        __syncthreads();
        // prefilter vs kept list: no break, 4-wide batched loads
        if (base > 0 && nL > 0) {
            int i = tid >> 1, half = tid & 1;
            if (i < m) {
                float4 bb = sbox[base + i];
                float ab = sar[base + i];
                bool dead = false;
                int k = half;
                for (; k + 6 < nL; k += 8) {
                    float4 c0 = lbox[k],     c1 = lbox[k + 2];
                    float4 c2 = lbox[k + 4], c3 = lbox[k + 6];
                    float r0 = lar[k],     r1 = lar[k + 2];
                    float r2 = lar[k + 4], r3 = lar[k + 6];
                    dead |= iou_gt(c0, r0, bb, ab);
                    dead |= iou_gt(c1, r1, bb, ab);
                    dead |= iou_gt(c2, r2, bb, ab);
                    dead |= iou_gt(c3, r3, bb, ab);
                }
                for (; k < nL; k += 2)
                    dead |= iou_gt(lbox[k], lar[k], bb, ab);
                if (dead) atomicOr(&pf[i >> 5], 1u << (i & 31));
            }
        }
        // triangular IoU mask; job remap: lanes share w, consecutive i ->
        // warp-uniform inner trip counts (divergence only at the diagonal)
#pragma unroll
        for (int q = 0; q < 4; ++q) {
            int jid = tid + q * 512;
            int i = jid & 255, w = jid >> 8;     // w in 0..7
            int jn = i - w * 32; if (jn > 32) jn = 32;
            if (i < m && jn > 0) {
                float4 bi = sbox[base + i];
                float ai = sar[base + i];
                unsigned bits = 0u;
                int j0 = base + w * 32;
                int l = 0;
                for (; l + 4 <= jn; l += 4) {
                    float4 c0 = sbox[j0 + l],     c1 = sbox[j0 + l + 1];
                    float4 c2 = sbox[j0 + l + 2], c3 = sbox[j0 + l + 3];
                    float r0 = sar[j0 + l],     r1 = sar[j0 + l + 1];
                    float r2 = sar[j0 + l + 2], r3 = sar[j0 + l + 3];
                    if (iou_gt(bi, ai, c0, r0)) bits |= 1u << l;
                    if (iou_gt(bi, ai, c1, r1)) bits |= 1u << (l + 1);
                    if (iou_gt(bi, ai, c2, r2)) bits |= 1u << (l + 2);
                    if (iou_gt(bi, ai, c3, r3)) bits |= 1u << (l + 3);
                }
                for (; l < jn; ++l)
                    if (iou_gt(bi, ai, sbox[j0 + l], sar[j0 + l]))
                        bits |= 1u << l;
                colmask[i * 8 + w] = bits;
            } else if (i < m) {
                colmask[i * 8 + w] = 0u;
            }
        }
        __syncthreads();
        if (tid < 8) {
            int lo = tid * 32;
            unsigned valid;
            if (m >= lo + 32)      valid = FULLM;
            else if (m <= lo)      valid = 0u;
            else                   valid = (1u << (m - lo)) - 1u;
            kw[tid] = valid & ~pf[tid];
        }
        __syncthreads();
        for (;;) {
            if (tid == 0) s_flag = 0;
            int alive = 0;
            if (tid < m && !((pf[tid >> 5] >> (tid & 31)) & 1u)) {
                unsigned acc = 0u;
#pragma unroll
                for (int w = 0; w < 8; ++w) acc |= colmask[tid * 8 + w] & kw[w];
                alive = (acc == 0u);
            }
            __syncthreads();
            unsigned nw = __ballot_sync(FULLM, alive);
            if (tid < 256 && (tid & 31) == 0) {
                if (nw != kw[tid >> 5]) s_flag = 1;
                kw[tid >> 5] = nw;
            }
            __syncthreads();
            int done = !s_flag;
            __syncthreads();
            if (done) break;
        }
        if (tid < 8) {
            int s = 0;
            for (int w2 = 0; w2 < tid; ++w2) s += __popc(kw[w2]);
            psum[tid] = s;
        }
        __syncthreads();
        int nk = psum[7] + __popc(kw[7]);
        int take = TOPK - nL; if (take > nk) take = nk;
        if (tid < m && ((kw[tid >> 5] >> (tid & 31)) & 1u)) {
            int r = psum[tid >> 5] + __popc(kw[tid >> 5] & ((1u << (tid & 31)) - 1u));
            if (r < take) {
                int slot = nL + r;
                int gb = bc * TOPK + slot;
                g_kscore[gb] = ssc[base + tid];
                g_kbox[gb]   = sbox[base + tid];
                lbox[slot]   = sbox[base + tid];
                lar[slot]    = sar[base + tid];
            }
        }
        nL += take;
        __syncthreads();
    }
    if (tid == 0) g_kcount[bc] = nL;

    // ---- G: completion counter; last CTA of image runs the global top-200 ----
    if (tid == 0) {
        __threadfence();
        unsigned old = atomicInc(&g_done[b], NFG - 1);
        s_last = (old == NFG - 1);
    }
    __syncthreads();
    if (!s_last) return;
    __threadfence();

    // ---- H: per-image global top-200 (bucket) ----
    for (int i = tid; i < FBINS; i += 512) hist[i] = 0;
    if (tid == 0) { s_ftb = -1; s_sel = 0; }
    if (tid < NFG) skc[tid] = g_kcount[b * NFG + tid];
    __syncthreads();

    for (int idx = tid; idx < NFG * TOPK; idx += 512) {
        int c = idx / TOPK, slot = idx - c * TOPK;
        if (slot < skc[c]) {
            unsigned bits = __float_as_uint(g_kscore[(b * NFG + c) * TOPK + slot]);
            atomicAdd(&hist[finebin(bits)], 1);
        }
    }
    __syncthreads();

    int total2 = suffix_scan_2048(hist, tid, sfx, &above);
    {
        int need = total2 < TOPK ? total2 : TOPK;
        if (need > 0) {
#pragma unroll
            for (int q = 0; q < 4; ++q) {
                int nxt = (q < 3) ? sfx[q + 1] : above;
                if (sfx[q] >= need && nxt < need) {
                    s_ftb = tid * 4 + q;
                    s_sel = sfx[q];
                }
            }
        }
    }
    __syncthreads();
    const int ftb2 = s_ftb;
    int count2 = s_sel; if (count2 > TOPK) count2 = TOPK; if (count2 > 512) count2 = 512;

    if (ftb2 >= 0) {
        for (int idx = tid; idx < NFG * TOPK; idx += 512) {
            int c = idx / TOPK, slot = idx - c * TOPK;
            if (slot < skc[c]) {
                unsigned bits = __float_as_uint(g_kscore[(b * NFG + c) * TOPK + slot]);
                int fb = (int)finebin(bits);
                if (fb >= ftb2) {
                    int pos = atomicAdd(&hist[fb], 1);
                    if (pos < 512)
                        dest[pos] = ((unsigned long long)bits << 32) |
                                    (0xFFFFFFFFu - (unsigned)(c * 256 + slot));
                }
            }
        }
        __syncthreads();
        for (int fb = ftb2 + tid; fb < FBINS; fb += 512) {
            int lo = (fb == FBINS - 1) ? 0 : hist[fb + 1];
            int hi = hist[fb];
            if (hi > 512) hi = 512;
            if (lo > hi) lo = hi;
            for (int x = lo + 1; x < hi; ++x) {
                unsigned long long key = dest[x];
                int y = x - 1;
                while (y >= lo && dest[y] < key) { dest[y + 1] = dest[y]; --y; }
                dest[y + 1] = key;
            }
        }
        __syncthreads();
    }

    if (tid < TOPK) {
        float b0 = 0.f, b1 = 0.f, b2 = 0.f, b3 = 0.f, sco = 0.f, lab = 0.f;
        if (tid < count2) {
            unsigned long long key = dest[tid];
            unsigned code = 0xFFFFFFFFu - (unsigned)(key & 0xFFFFFFFFu);
            int c    = (int)(code >> 8);
            int slot = (int)(code & 255u);
            float4 kb = g_kbox[(b * NFG + c) * TOPK + slot];
            sco = __uint_as_float((unsigned)(key >> 32));
            b0 = kb.x; b1 = kb.y; b2 = kb.z; b3 = kb.w;
            lab = (float)(c + 1);
        }
        out[(b * TOPK + tid) * 4 + 0] = b0;
        out[(b * TOPK + tid) * 4 + 1] = b1;
        out[(b * TOPK + tid) * 4 + 2] = b2;
        out[(b * TOPK + tid) * 4 + 3] = b3;
        out[BATCH * TOPK * 4 + b * TOPK + tid] = sco;
        out[BATCH * TOPK * 5 + b * TOPK + tid] = lab;
    }
}

// ============================================================
extern "C" void kernel_launch(void* const* d_in, const int* in_sizes, int n_in,
                              void* d_out, int out_size) {
    const float* cls  = (const float*)d_in[0];  // [8, 8732, 21]
    const float* loc  = (const float*)d_in[1];  // [8, 8732, 4]
    const float* anch = (const float*)d_in[2];  // [8732, 4]
    float* out = (float*)d_out;

    prep_kernel<<<TR_BLOCKS, 256>>>(cls);
    nms_kernel<<<BATCH * NFG, 512>>>(loc, anch, out);
}

// round 11
// speedup vs baseline: 3.0137x; 1.3027x over previous
#include <cuda_runtime.h>
#include <math.h>

#define BATCH   8
#define NA      8732
#define NAP     8736
#define NC      21
#define NFG     20
#define TOPK    200
#define PRE     1024
#define DCAP    1280
#define FBINS   2048
#define FSH     12
#define BASEB   0x3F000000u
#define CONF_T  0.5f
#define FULLM   0xFFFFFFFFu

// Exact midpoint for  div.rn.f32(inter,union) > 0.45f  (see derivation):
// 0.45f = 0x3EE66666 (even mantissa); ulp = 2^-25; midpoint = c + 2^-26.
// (double)inter and MID*(double)union are exact -> bit-identical decisions.
#define IOU_MID (0.449999988079071044921875 + 1.490116119384765625e-8)

// ---- scratch (static __device__, allocation-free) ----
__device__ float    g_clsT[BATCH * NFG * NAP];   // transposed scores; pad stays 0
__device__ float    g_kscore[BATCH * NFG * TOPK];
__device__ float4   g_kbox[BATCH * NFG * TOPK];
__device__ int      g_kcount[BATCH * NFG];
__device__ unsigned g_done[BATCH];               // wrap counters (stay 0 after run)

#define TR_TILE   128
#define TR_TPB    ((NA + TR_TILE - 1) / TR_TILE)   // 69
#define TR_BLOCKS (BATCH * TR_TPB)

// Branchless, division-free, BIT-EXACT equivalent of:
//   w=max(min(pz,qz)-max(px,qx)+1,0); h=...; inter=w*h;
//   inter/(pa+qa-inter) > 0.45f      (IEEE div.rn)
__device__ __forceinline__ bool iou_hit(float4 p, float pa, float4 q, float qa) {
    float w = fminf(p.z, q.z) - fmaxf(p.x, q.x) + 1.0f;
    float h = fminf(p.w, q.w) - fmaxf(p.y, q.y) + 1.0f;
    float inter = fmaxf(w, 0.0f) * fmaxf(h, 0.0f);
    float uni = pa + qa - inter;                 // same operand order as before
    return (double)inter > IOU_MID * (double)uni;
}

__device__ __forceinline__ unsigned finebin(unsigned bits) {
    unsigned fb = (bits - BASEB) >> FSH;
    return fb > (FBINS - 1u) ? (FBINS - 1u) : fb;
}

// Block suffix-scan over FBINS bins (512 threads, 4 consecutive bins each).
__device__ __forceinline__ int suffix_scan_2048(int* hist, int tid, int* sfx,
                                                int* above_out) {
    __shared__ int ws[16];
    __shared__ int s_total;
    const int lane = tid & 31, wid = tid >> 5;
    int b4 = tid * 4;
    int h0 = hist[b4], h1 = hist[b4 + 1], h2 = hist[b4 + 2], h3 = hist[b4 + 3];
    sfx[3] = h3; sfx[2] = h2 + sfx[3]; sfx[1] = h1 + sfx[2]; sfx[0] = h0 + sfx[1];
    int T = sfx[0], S = T;
#pragma unroll
    for (int off = 1; off < 32; off <<= 1) {
        int v = __shfl_down_sync(FULLM, S, off);
        if (lane + off < 32) S += v;
    }
    if (lane == 0) ws[wid] = S;
    __syncthreads();
    if (tid < 16) {
        int W = ws[tid];
#pragma unroll
        for (int off = 1; off < 16; off <<= 1) {
            int v = __shfl_down_sync(0x0000FFFFu, W, off);
            if (tid + off < 16) W += v;
        }
        ws[tid] = W;
        if (tid == 0) s_total = W;
    }
    __syncthreads();
    int above = ((wid < 15) ? ws[wid + 1] : 0) + (S - T);
    sfx[0] += above; sfx[1] += above; sfx[2] += above; sfx[3] += above;
    hist[b4]     = sfx[1];
    hist[b4 + 1] = sfx[2];
    hist[b4 + 2] = sfx[3];
    hist[b4 + 3] = above;
    *above_out = above;
    return s_total;
}

// ============================================================
// Kernel 1: transpose cls [b][a][c] -> g_clsT [b][c][a] (coalesced).
// ============================================================
__global__ void prep_kernel(const float* __restrict__ cls) {
    __shared__ float sh[TR_TILE * NC];
    int t = blockIdx.x;
    int b = t / TR_TPB, tile = t % TR_TPB;
    int a0 = tile * TR_TILE;
    int n = NA - a0; if (n > TR_TILE) n = TR_TILE;
    const float* src = cls + ((size_t)(b * NA + a0)) * NC;
    for (int i = threadIdx.x; i < n * NC; i += 256) sh[i] = src[i];
    __syncthreads();
    int half = threadIdx.x >> 7;
    int t2 = threadIdx.x & 127;
    if (t2 < n) {
        for (int c = half * 10; c < half * 10 + 10; ++c)
            g_clsT[((size_t)(b * NFG + c)) * NAP + a0 + t2] = sh[t2 * NC + c + 1];
    }
}

// ============================================================
// Kernel 2: bucket top-1024 + fixpoint greedy NMS; last CTA per image
// also performs the per-image global top-200 (fused).
// ============================================================
__global__ __launch_bounds__(512, 2) void nms_kernel(const float* __restrict__ loc,
                                                     const float* __restrict__ anch,
                                                     float* __restrict__ out) {
    const int bc  = blockIdx.x;
    const int b   = bc / NFG;
    const int c20 = bc % NFG;
    const int tid = threadIdx.x;

    __shared__ __align__(16) int histbuf[FBINS];             // 8KB
    __shared__ __align__(16) unsigned long long dest[DCAP];  // 10KB
    __shared__ __align__(16) float4 sbox[PRE];               // 16KB
    __shared__ float  sar[PRE], ssc[PRE];                    // 8KB
    __shared__ unsigned kw[8], pf[8];
    __shared__ int psum[8];
    __shared__ int skc[NFG];
    __shared__ int s_fl[2];
    __shared__ int s_ftb, s_sel, s_last;

    int* hist = histbuf;
    unsigned* colmask = (unsigned*)histbuf;
    float4* lbox = (float4*)dest;
    float*  lar  = (float*)(dest + 512);

    for (int i = tid; i < FBINS; i += 512) hist[i] = 0;
    if (tid == 0) { s_ftb = -1; s_sel = 0; }
    __syncthreads();

    const float4* scol4 = reinterpret_cast<const float4*>(
        g_clsT + ((size_t)(b * NFG + c20)) * NAP);

    // ---- A: fine histogram, vectorized float4 (pad scores are 0) ----
    for (int v = tid; v < NAP / 4; v += 512) {
        float4 s4 = scol4[v];
        if (s4.x > CONF_T) atomicAdd(&hist[finebin(__float_as_uint(s4.x))], 1);
        if (s4.y > CONF_T) atomicAdd(&hist[finebin(__float_as_uint(s4.y))], 1);
        if (s4.z > CONF_T) atomicAdd(&hist[finebin(__float_as_uint(s4.z))], 1);
        if (s4.w > CONF_T) atomicAdd(&hist[finebin(__float_as_uint(s4.w))], 1);
    }
    __syncthreads();

    // ---- B: suffix scan; unique-boundary threshold (no atomics) ----
    int sfx[4], above;
    int total = suffix_scan_2048(hist, tid, sfx, &above);
    {
        int need = total < PRE ? total : PRE;
        if (need > 0) {
#pragma unroll
            for (int q = 0; q < 4; ++q) {
                int nxt = (q < 3) ? sfx[q + 1] : above;
                if (sfx[q] >= need && nxt < need) {
                    s_ftb = tid * 4 + q;
                    s_sel = sfx[q];
                }
            }
        }
    }
    __syncthreads();
    const int ftb = s_ftb;
    int count = s_sel; if (count > PRE) count = PRE; if (count > DCAP) count = DCAP;

    // ---- C: scatter to exact positions + per-bin tie sort ----
    if (ftb >= 0) {
        for (int v = tid; v < NAP / 4; v += 512) {
            float4 s4 = scol4[v];
            float sv[4] = {s4.x, s4.y, s4.z, s4.w};
#pragma unroll
            for (int k = 0; k < 4; ++k) {
                if (sv[k] > CONF_T) {
                    unsigned bits = __float_as_uint(sv[k]);
                    int fb = (int)finebin(bits);
                    if (fb >= ftb) {
                        int pos = atomicAdd(&hist[fb], 1);
                        if (pos < DCAP)
                            dest[pos] = ((unsigned long long)bits << 32) |
                                        (unsigned)(65535 - (4 * v + k));
                    }
                }
            }
        }
        __syncthreads();
        for (int fb = ftb + tid; fb < FBINS; fb += 512) {
            int lo = (fb == FBINS - 1) ? 0 : hist[fb + 1];
            int hi = hist[fb];
            if (hi > DCAP) hi = DCAP;
            if (lo > hi) lo = hi;
            for (int x = lo + 1; x < hi; ++x) {
                unsigned long long key = dest[x];
                int y = x - 1;
                while (y >= lo && dest[y] < key) { dest[y + 1] = dest[y]; --y; }
                dest[y + 1] = key;
            }
        }
        __syncthreads();
    }

    // ---- E: decode candidate boxes best-first ----
    const float4* loc4  = reinterpret_cast<const float4*>(loc);
    const float4* anch4 = reinterpret_cast<const float4*>(anch);
#pragma unroll
    for (int t = 0; t < 2; ++t) {
        int r = tid + t * 512;
        if (r < count) {
            unsigned long long key = dest[r];
            int a = 65535 - (int)(key & 0xFFFFu);
            float4 l  = loc4[b * NA + a];
            float4 an = anch4[a];
            float cx = an.x + l.x * 0.1f * an.z;
            float cy = an.y + l.y * 0.1f * an.w;
            float w  = an.z * expf(l.z * 0.2f);
            float h  = an.w * expf(l.w * 0.2f);
            float x1 = cx - w * 0.5f;
            float y1 = cy - h * 0.5f;
            float4 bb;
            bb.x = fminf(fmaxf(x1 * 300.0f, 0.0f), 299.0f);
            bb.y = fminf(fmaxf(y1 * 300.0f, 0.0f), 299.0f);
            bb.z = fminf(fmaxf((x1 + w) * 300.0f, 0.0f), 299.0f);
            bb.w = fminf(fmaxf((y1 + h) * 300.0f, 0.0f), 299.0f);
            sbox[r] = bb;
            sar[r] = (bb.z - bb.x + 1.0f) * (bb.w - bb.y + 1.0f);
            ssc[r] = __uint_as_float((unsigned)(key >> 32));
        }
    }
    __syncthreads();

    // ---- F: tiled greedy NMS via parallel fixpoint ----
    int nL = 0;
    for (int base = 0; base < count && nL < TOPK; base += 256) {
        int m = count - base; if (m > 256) m = 256;
        if (tid < 8) pf[tid] = 0u;
        __syncthreads();
        // prefilter vs kept list: branchless IoU, 4-wide batched
        if (base > 0 && nL > 0) {
            int i = tid >> 1, half = tid & 1;
            if (i < m) {
                float4 bb = sbox[base + i];
                float ab = sar[base + i];
                bool dead = false;
                int k = half;
                for (; k + 6 < nL; k += 8) {
                    dead |= iou_hit(lbox[k],     lar[k],     bb, ab);
                    dead |= iou_hit(lbox[k + 2], lar[k + 2], bb, ab);
                    dead |= iou_hit(lbox[k + 4], lar[k + 4], bb, ab);
                    dead |= iou_hit(lbox[k + 6], lar[k + 6], bb, ab);
                }
                for (; k < nL; k += 2)
                    dead |= iou_hit(lbox[k], lar[k], bb, ab);
                if (dead) atomicOr(&pf[i >> 5], 1u << (i & 31));
            }
        }
        // triangular IoU mask; lanes share w, consecutive i
#pragma unroll
        for (int q = 0; q < 4; ++q) {
            int jid = tid + q * 512;
            int i = jid & 255, w = jid >> 8;
            int jn = i - w * 32; if (jn > 32) jn = 32;
            if (i < m && jn > 0) {
                float4 bi = sbox[base + i];
                float ai = sar[base + i];
                unsigned bits = 0u;
                int j0 = base + w * 32;
                int l = 0;
                for (; l + 4 <= jn; l += 4) {
                    if (iou_hit(bi, ai, sbox[j0 + l],     sar[j0 + l]))     bits |= 1u << l;
                    if (iou_hit(bi, ai, sbox[j0 + l + 1], sar[j0 + l + 1])) bits |= 1u << (l + 1);
                    if (iou_hit(bi, ai, sbox[j0 + l + 2], sar[j0 + l + 2])) bits |= 1u << (l + 2);
                    if (iou_hit(bi, ai, sbox[j0 + l + 3], sar[j0 + l + 3])) bits |= 1u << (l + 3);
                }
                for (; l < jn; ++l)
                    if (iou_hit(bi, ai, sbox[j0 + l], sar[j0 + l]))
                        bits |= 1u << l;
                colmask[i * 8 + w] = bits;
            } else if (i < m) {
                colmask[i * 8 + w] = 0u;
            }
        }
        __syncthreads();
        if (tid < 8) {
            int lo = tid * 32;
            unsigned valid;
            if (m >= lo + 32)      valid = FULLM;
            else if (m <= lo)      valid = 0u;
            else                   valid = (1u << (m - lo)) - 1u;
            kw[tid] = valid & ~pf[tid];
        }
        if (tid == 0) { s_fl[0] = 0; s_fl[1] = 0; }
        // cache own colmask row + precondition in registers
        unsigned cm[8];
        int pre_ok = 0;
        __syncthreads();
        if (tid < m && !((pf[tid >> 5] >> (tid & 31)) & 1u)) {
            pre_ok = 1;
#pragma unroll
            for (int w = 0; w < 8; ++w) cm[w] = colmask[tid * 8 + w];
        }
        // fixpoint: 2 barriers per sweep, parity convergence flags
        int p = 0;
        for (;;) {
            int alive = 0;
            if (pre_ok) {
                unsigned acc = (cm[0] & kw[0]) | (cm[1] & kw[1]) |
                               (cm[2] & kw[2]) | (cm[3] & kw[3]) |
                               (cm[4] & kw[4]) | (cm[5] & kw[5]) |
                               (cm[6] & kw[6]) | (cm[7] & kw[7]);
                alive = (acc == 0u);
            }
            __syncthreads();                       // all reads of kw done
            unsigned nw = __ballot_sync(FULLM, alive);
            if (tid < 256 && (tid & 31) == 0) {
                if (nw != kw[tid >> 5]) s_fl[p] = 1;
                kw[tid >> 5] = nw;
            }
            if (tid == 0) s_fl[p ^ 1] = 0;
            __syncthreads();                       // kw + flags visible
            if (!s_fl[p]) break;
            p ^= 1;
        }
        if (tid < 8) {
            int s = 0;
            for (int w2 = 0; w2 < tid; ++w2) s += __popc(kw[w2]);
            psum[tid] = s;
        }
        __syncthreads();
        int nk = psum[7] + __popc(kw[7]);
        int take = TOPK - nL; if (take > nk) take = nk;
        if (tid < m && ((kw[tid >> 5] >> (tid & 31)) & 1u)) {
            int r = psum[tid >> 5] + __popc(kw[tid >> 5] & ((1u << (tid & 31)) - 1u));
            if (r < take) {
                int slot = nL + r;
                int gb = bc * TOPK + slot;
                g_kscore[gb] = ssc[base + tid];
                g_kbox[gb]   = sbox[base + tid];
                lbox[slot]   = sbox[base + tid];
                lar[slot]    = sar[base + tid];
            }
        }
        nL += take;
        __syncthreads();
    }
    if (tid == 0) g_kcount[bc] = nL;

    // ---- G: completion counter; last CTA of image runs the global top-200 ----
    if (tid == 0) {
        __threadfence();
        unsigned old = atomicInc(&g_done[b], NFG - 1);
        s_last = (old == NFG - 1);
    }
    __syncthreads();
    if (!s_last) return;
    __threadfence();

    // ---- H: per-image global top-200 (bucket) ----
    for (int i = tid; i < FBINS; i += 512) hist[i] = 0;
    if (tid == 0) { s_ftb = -1; s_sel = 0; }
    if (tid < NFG) skc[tid] = g_kcount[b * NFG + tid];
    __syncthreads();

    for (int idx = tid; idx < NFG * TOPK; idx += 512) {
        int c = idx / TOPK, slot = idx - c * TOPK;
        if (slot < skc[c]) {
            unsigned bits = __float_as_uint(g_kscore[(b * NFG + c) * TOPK + slot]);
            atomicAdd(&hist[finebin(bits)], 1);
        }
    }
    __syncthreads();

    int total2 = suffix_scan_2048(hist, tid, sfx, &above);
    {
        int need = total2 < TOPK ? total2 : TOPK;
        if (need > 0) {
#pragma unroll
            for (int q = 0; q < 4; ++q) {
                int nxt = (q < 3) ? sfx[q + 1] : above;
                if (sfx[q] >= need && nxt < need) {
                    s_ftb = tid * 4 + q;
                    s_sel = sfx[q];
                }
            }
        }
    }
    __syncthreads();
    const int ftb2 = s_ftb;
    int count2 = s_sel; if (count2 > TOPK) count2 = TOPK; if (count2 > 512) count2 = 512;

    if (ftb2 >= 0) {
        for (int idx = tid; idx < NFG * TOPK; idx += 512) {
            int c = idx / TOPK, slot = idx - c * TOPK;
            if (slot < skc[c]) {
                unsigned bits = __float_as_uint(g_kscore[(b * NFG + c) * TOPK + slot]);
                int fb = (int)finebin(bits);
                if (fb >= ftb2) {
                    int pos = atomicAdd(&hist[fb], 1);
                    if (pos < 512)
                        dest[pos] = ((unsigned long long)bits << 32) |
                                    (0xFFFFFFFFu - (unsigned)(c * 256 + slot));
                }
            }
        }
        __syncthreads();
        for (int fb = ftb2 + tid; fb < FBINS; fb += 512) {
            int lo = (fb == FBINS - 1) ? 0 : hist[fb + 1];
            int hi = hist[fb];
            if (hi > 512) hi = 512;
            if (lo > hi) lo = hi;
            for (int x = lo + 1; x < hi; ++x) {
                unsigned long long key = dest[x];
                int y = x - 1;
                while (y >= lo && dest[y] < key) { dest[y + 1] = dest[y]; --y; }
                dest[y + 1] = key;
            }
        }
        __syncthreads();
    }

    if (tid < TOPK) {
        float b0 = 0.f, b1 = 0.f, b2 = 0.f, b3 = 0.f, sco = 0.f, lab = 0.f;
        if (tid < count2) {
            unsigned long long key = dest[tid];
            unsigned code = 0xFFFFFFFFu - (unsigned)(key & 0xFFFFFFFFu);
            int c    = (int)(code >> 8);
            int slot = (int)(code & 255u);
            float4 kb = g_kbox[(b * NFG + c) * TOPK + slot];
            sco = __uint_as_float((unsigned)(key >> 32));
            b0 = kb.x; b1 = kb.y; b2 = kb.z; b3 = kb.w;
            lab = (float)(c + 1);
        }
        out[(b * TOPK + tid) * 4 + 0] = b0;
        out[(b * TOPK + tid) * 4 + 1] = b1;
        out[(b * TOPK + tid) * 4 + 2] = b2;
        out[(b * TOPK + tid) * 4 + 3] = b3;
        out[BATCH * TOPK * 4 + b * TOPK + tid] = sco;
        out[BATCH * TOPK * 5 + b * TOPK + tid] = lab;
    }
}

// ============================================================
extern "C" void kernel_launch(void* const* d_in, const int* in_sizes, int n_in,
                              void* d_out, int out_size) {
    const float* cls  = (const float*)d_in[0];  // [8, 8732, 21]
    const float* loc  = (const float*)d_in[1];  // [8, 8732, 4]
    const float* anch = (const float*)d_in[2];  // [8732, 4]
    float* out = (float*)d_out;

    prep_kernel<<<TR_BLOCKS, 256>>>(cls);
    nms_kernel<<<BATCH * NFG, 512>>>(loc, anch, out);
}